// round 4
// baseline (speedup 1.0000x reference)
#include <cuda_runtime.h>
#include <cstdint>

#define NTOK   2048
#define DMODEL 512
#define DFFN   2048
#define NH     8
#define DHEAD  64
#define NLAYER 6

// ---------------- device scratch (static, no allocation) ----------------
__device__ float g_X[NTOK * DMODEL];
__device__ float g_Q[NTOK * DMODEL];
__device__ float g_Kb[NTOK * DMODEL];
__device__ float g_Vb[NTOK * DMODEL];
__device__ float g_S[(size_t)NH * NTOK * NTOK];          // 128 MB
__device__ float2 g_part[NH * 8 * NTOK];
__device__ float g_lse[NH * NTOK];
__device__ float g_corr[NH * DHEAD];
__device__ float g_A[NTOK * DMODEL];
__device__ float g_Z[NTOK * DMODEL];
__device__ float g_F[NTOK * DFFN];
__device__ float g_P[4 * NTOK * DMODEL];                 // split-K partials (16 MB)

// ---------------- fast exp (FMA-only, no MUFU) ----------------
__device__ __forceinline__ float fexp(float x) {
    x = fmaxf(x, -87.0f);
    float t = x * 1.4426950408889634f;
    const float big = 12582912.0f;                        // 1.5 * 2^23
    float r = __fadd_rn(t, big) - big;                    // round(t)
    float f = t - r;                                      // [-0.5, 0.5]
    float p = 1.5403530e-4f;
    p = fmaf(p, f, 1.33335581e-3f);
    p = fmaf(p, f, 9.61812911e-3f);
    p = fmaf(p, f, 5.55041087e-2f);
    p = fmaf(p, f, 2.40226507e-1f);
    p = fmaf(p, f, 6.93147181e-1f);
    p = fmaf(p, f, 1.0f);
    int e = (int)r;
    return p * __int_as_float((e + 127) << 23);
}

// ---------------- embedding + positional encoding ----------------
__global__ void embed_pe(const int* __restrict__ ids, const float* __restrict__ E,
                         float* __restrict__ X) {
    int n = blockIdx.x, t = threadIdx.x;                  // 128 threads
    int id = ids[n];
    float4 e = *(const float4*)&E[(size_t)id * DMODEL + t * 4];
    float ev[4] = {e.x, e.y, e.z, e.w};
    float pos = (float)(n + 1);
    float ov[4];
#pragma unroll
    for (int i = 0; i < 4; i++) {
        int d = t * 4 + i;
        int de = d & ~1;
        float f = expf((float)de * (-9.210340371976184f / 512.0f));
        float arg = pos * f;
        float pe = (d & 1) ? cosf(arg) : sinf(arg);
        ov[i] = ev[i] + pe;
    }
    *(float4*)&X[(size_t)n * DMODEL + t * 4] = *(float4*)ov;
}

// ---------------- tiled SGEMM, NN, batched, optional split-K ----------------
// C[b][m][n] = sum_k A[b][m][k] * B[b][k][n]  (+bias +res, relu) or raw partial to P.
// BM in {64,128}, BN=64, BK=16, 256 threads, TM = BM/16, TN=4.
template <int BM, int TM>
__global__ void __launch_bounds__(256, 2)
sgemm_nn(const float* __restrict__ Ag, const float* __restrict__ Bg,
         float* __restrict__ Cg, float* __restrict__ Pbuf,
         int M, int Nn, int K, int lda, int ldb, int ldc,
         long long sA, long long sB, long long sC,
         const float* __restrict__ biasg, int sBias,
         const float* __restrict__ resg, int ldr, long long sR,
         int relu, int nTilesX, int kSplits) {
    const int xt = blockIdx.x % nTilesX;
    const int split = blockIdx.x / nTilesX;
    const int b = blockIdx.z;
    const int kLen = K / kSplits;
    const int kStart = split * kLen;

    const float* A = Ag + (size_t)b * sA + kStart;
    const float* B = Bg + (size_t)b * sB + (size_t)kStart * ldb;

    __shared__ float As[16][BM];
    __shared__ float Bs[16][68];

    const int tid = threadIdx.x;
    const int m0 = blockIdx.y * BM;
    const int n0 = xt * 64;
    const int ty = tid >> 4;
    const int tx = tid & 15;

    float acc[TM][4];
#pragma unroll
    for (int i = 0; i < TM; i++)
#pragma unroll
        for (int j = 0; j < 4; j++) acc[i][j] = 0.f;

    constexpr int LA = (BM * 16) / 1024;   // float4 A-loads per thread (1 or 2)
    int mA[LA], kgA[LA];
#pragma unroll
    for (int r = 0; r < LA; r++) {
        int idx = tid + r * 256;
        mA[r] = idx % BM;
        kgA[r] = idx / BM;
    }
    const int bk = ty;
    const int bn = tx << 2;

    for (int k0 = 0; k0 < kLen; k0 += 16) {
        float4 av[LA];
#pragma unroll
        for (int r = 0; r < LA; r++)
            av[r] = *(const float4*)&A[(size_t)(m0 + mA[r]) * lda + k0 + (kgA[r] << 2)];
        float4 bv = *(const float4*)&B[(size_t)(k0 + bk) * ldb + n0 + bn];
        __syncthreads();
#pragma unroll
        for (int r = 0; r < LA; r++) {
            int k4 = kgA[r] << 2;
            As[k4 + 0][mA[r]] = av[r].x;
            As[k4 + 1][mA[r]] = av[r].y;
            As[k4 + 2][mA[r]] = av[r].z;
            As[k4 + 3][mA[r]] = av[r].w;
        }
        *(float4*)&Bs[bk][bn] = bv;
        __syncthreads();
#pragma unroll
        for (int kk = 0; kk < 16; kk++) {
            float ar[TM];
#pragma unroll
            for (int i = 0; i < TM; i += 4) {
                float4 t4 = *(const float4*)&As[kk][ty * TM + i];
                ar[i] = t4.x; ar[i + 1] = t4.y; ar[i + 2] = t4.z; ar[i + 3] = t4.w;
            }
            float4 b4 = *(const float4*)&Bs[kk][tx << 2];
            float br[4] = {b4.x, b4.y, b4.z, b4.w};
#pragma unroll
            for (int i = 0; i < TM; i++)
#pragma unroll
                for (int j = 0; j < 4; j++)
                    acc[i][j] = fmaf(ar[i], br[j], acc[i][j]);
        }
    }

    if (kSplits > 1) {
        float* P = Pbuf + (size_t)split * ((size_t)gridDim.z * M * Nn) + (size_t)b * M * Nn;
#pragma unroll
        for (int i = 0; i < TM; i++) {
            int m = m0 + ty * TM + i;
            *(float4*)&P[(size_t)m * Nn + n0 + (tx << 2)] = *(float4*)acc[i];
        }
    } else {
        float* C = Cg + (size_t)b * sC;
        const float* bi = biasg ? biasg + (size_t)b * sBias : nullptr;
        const float* R = resg ? resg + (size_t)b * sR : nullptr;
#pragma unroll
        for (int i = 0; i < TM; i++) {
            int m = m0 + ty * TM + i;
            int n = n0 + (tx << 2);
            float4 v = *(float4*)acc[i];
            if (bi) { v.x += bi[n]; v.y += bi[n + 1]; v.z += bi[n + 2]; v.w += bi[n + 3]; }
            if (R) {
                float4 r4 = *(const float4*)&R[(size_t)m * ldr + n];
                v.x += r4.x; v.y += r4.y; v.z += r4.z; v.w += r4.w;
            }
            if (relu) {
                v.x = fmaxf(v.x, 0.f); v.y = fmaxf(v.y, 0.f);
                v.z = fmaxf(v.z, 0.f); v.w = fmaxf(v.w, 0.f);
            }
            *(float4*)&C[(size_t)m * ldc + n] = v;
        }
    }
}

// ---------------- split-K reduction + epilogue ----------------
__global__ void reduce_split(const float* __restrict__ P, float* __restrict__ C,
                             int M, int Nn, int ldc, long long sC, int nsplit,
                             const float* __restrict__ bias, int sBias,
                             const float* __restrict__ res, int ldr, long long sR,
                             int relu, int batch) {
    size_t perBatch = (size_t)M * Nn;
    size_t total4 = (size_t)batch * perBatch / 4;
    size_t idx = (size_t)blockIdx.x * blockDim.x + threadIdx.x;
    if (idx >= total4) return;
    size_t e4 = idx * 4;
    int b = (int)(e4 / perBatch);
    size_t r = e4 % perBatch;
    int m = (int)(r / Nn);
    int n = (int)(r % Nn);
    size_t splitStride = (size_t)batch * perBatch;
    float4 v = *(const float4*)&P[e4];
    for (int s = 1; s < nsplit; s++) {
        float4 p = *(const float4*)&P[(size_t)s * splitStride + e4];
        v.x += p.x; v.y += p.y; v.z += p.z; v.w += p.w;
    }
    if (bias) {
        const float* bi = bias + (size_t)b * sBias;
        v.x += bi[n]; v.y += bi[n + 1]; v.z += bi[n + 2]; v.w += bi[n + 3];
    }
    if (res) {
        float4 r4 = *(const float4*)&res[(size_t)b * sR + (size_t)m * ldr + n];
        v.x += r4.x; v.y += r4.y; v.z += r4.z; v.w += r4.w;
    }
    if (relu) {
        v.x = fmaxf(v.x, 0.f); v.y = fmaxf(v.y, 0.f);
        v.z = fmaxf(v.z, 0.f); v.w = fmaxf(v.w, 0.f);
    }
    *(float4*)&C[(size_t)b * sC + (size_t)m * ldc + n] = v;
}

// ---------------- QK^T (NT), per head, scaled ----------------
__global__ void __launch_bounds__(256, 2)
sgemm_nt_qk(const float* __restrict__ Qg, const float* __restrict__ Kg,
            float* __restrict__ Sg, float alpha) {
    const int h = blockIdx.z;
    const float* A = Qg + h * 64;                         // [2048,64] lda=512
    const float* B = Kg + h * 64;                         // [2048,64] ldb=512
    float* C = Sg + (size_t)h * NTOK * NTOK;              // ldc=2048

    __shared__ float As[16][128];
    __shared__ float Bs[16][68];

    const int tid = threadIdx.x;
    const int m0 = blockIdx.y * 128;
    const int n0 = blockIdx.x * 64;
    const int ty = tid >> 4, tx = tid & 15;
    const int am = tid & 127, akg = tid >> 7;             // A: 2 float4 along k
    const int bn2 = tid >> 2, bkg = tid & 3;              // B: 1 float4 along k

    float acc[8][4];
#pragma unroll
    for (int i = 0; i < 8; i++)
#pragma unroll
        for (int j = 0; j < 4; j++) acc[i][j] = 0.f;

    for (int k0 = 0; k0 < 64; k0 += 16) {
        float4 a0 = *(const float4*)&A[(size_t)(m0 + am) * DMODEL + k0 + (akg << 2)];
        float4 a1 = *(const float4*)&A[(size_t)(m0 + am) * DMODEL + k0 + ((akg + 2) << 2)];
        float4 bv = *(const float4*)&B[(size_t)(n0 + bn2) * DMODEL + k0 + (bkg << 2)];
        __syncthreads();
        int k4 = akg << 2;
        As[k4 + 0][am] = a0.x; As[k4 + 1][am] = a0.y; As[k4 + 2][am] = a0.z; As[k4 + 3][am] = a0.w;
        k4 = (akg + 2) << 2;
        As[k4 + 0][am] = a1.x; As[k4 + 1][am] = a1.y; As[k4 + 2][am] = a1.z; As[k4 + 3][am] = a1.w;
        int kb = bkg << 2;
        Bs[kb + 0][bn2] = bv.x; Bs[kb + 1][bn2] = bv.y; Bs[kb + 2][bn2] = bv.z; Bs[kb + 3][bn2] = bv.w;
        __syncthreads();
#pragma unroll
        for (int kk = 0; kk < 16; kk++) {
            float ar[8];
            float4 t0 = *(const float4*)&As[kk][ty * 8];
            float4 t1 = *(const float4*)&As[kk][ty * 8 + 4];
            ar[0] = t0.x; ar[1] = t0.y; ar[2] = t0.z; ar[3] = t0.w;
            ar[4] = t1.x; ar[5] = t1.y; ar[6] = t1.z; ar[7] = t1.w;
            float4 b4 = *(const float4*)&Bs[kk][tx << 2];
            float br[4] = {b4.x, b4.y, b4.z, b4.w};
#pragma unroll
            for (int i = 0; i < 8; i++)
#pragma unroll
                for (int j = 0; j < 4; j++)
                    acc[i][j] = fmaf(ar[i], br[j], acc[i][j]);
        }
    }
#pragma unroll
    for (int i = 0; i < 8; i++) {
        int m = m0 + ty * 8 + i;
        float4 v;
        v.x = acc[i][0] * alpha; v.y = acc[i][1] * alpha;
        v.z = acc[i][2] * alpha; v.w = acc[i][3] * alpha;
        *(float4*)&C[(size_t)m * NTOK + n0 + (tx << 2)] = v;
    }
}

// ---------------- column-wise logsumexp over query axis (segmented) ----------------
__global__ void lse_part_kernel(const float* __restrict__ S, float2* __restrict__ part) {
    int m = blockIdx.x * 256 + threadIdx.x;
    int seg = blockIdx.y;                                  // 0..7
    int h = blockIdx.z;
    const float* col = S + (size_t)h * NTOK * NTOK + (size_t)seg * (NTOK / 8) * NTOK + m;
    float mx = -3.0e38f, s = 0.f;
#pragma unroll 4
    for (int q = 0; q < NTOK / 8; q++) {
        float x = col[(size_t)q * NTOK];
        float nm = fmaxf(mx, x);
        s = fmaf(s, fexp(mx - nm), fexp(x - nm));
        mx = nm;
    }
    part[((size_t)h * 8 + seg) * NTOK + m] = make_float2(mx, s);
}

__global__ void lse_combine_kernel(const float2* __restrict__ part, float* __restrict__ lse) {
    int m = blockIdx.x * 256 + threadIdx.x;
    int h = blockIdx.y;
    float2 p[8];
    float mx = -3.0e38f;
#pragma unroll
    for (int s = 0; s < 8; s++) {
        p[s] = part[((size_t)h * 8 + s) * NTOK + m];
        mx = fmaxf(mx, p[s].x);
    }
    float sum = 0.f;
#pragma unroll
    for (int s = 0; s < 8; s++) sum += p[s].y * expf(p[s].x - mx);
    lse[h * NTOK + m] = mx + logf(sum);
}

// corr[h][v] = -sum_m lse[h,m] * V[m, h*64+v]
__global__ void corr_kernel(const float* __restrict__ lse, const float* __restrict__ Vb,
                            float* __restrict__ corr) {
    int h = blockIdx.x, t = threadIdx.x;
    int v = t & 63, seg = t >> 6;
    const float* Vp = Vb + h * 64 + v;
    const float* lp = lse + h * NTOK;
    float acc = 0.f;
    for (int m = seg * 512; m < seg * 512 + 512; m++)
        acc = fmaf(lp[m], Vp[(size_t)m * 512], acc);
    __shared__ float red[256];
    red[t] = acc;
    __syncthreads();
    if (t < 64) {
        float tot = red[t] + red[t + 64] + red[t + 128] + red[t + 192];
        corr[h * 64 + t] = -tot;
    }
}

// ---------------- layernorm (ddof=1, no eps, elementwise gain/bias) ----------------
__global__ void layernorm_kernel(const float* __restrict__ in, const float* __restrict__ g,
                                 const float* __restrict__ be, float* __restrict__ out) {
    int n = blockIdx.x, t = threadIdx.x;                   // 128 threads
    size_t base = (size_t)n * 512 + t * 4;
    float4 x = *(const float4*)&in[base];
    float s = x.x + x.y + x.z + x.w;
#pragma unroll
    for (int o = 16; o > 0; o >>= 1) s += __shfl_xor_sync(0xffffffffu, s, o);
    __shared__ float r1[4], r2[4];
    if ((t & 31) == 0) r1[t >> 5] = s;
    __syncthreads();
    float mean = (r1[0] + r1[1] + r1[2] + r1[3]) * (1.0f / 512.0f);
    float d0 = x.x - mean, d1 = x.y - mean, d2 = x.z - mean, d3 = x.w - mean;
    float ss = d0 * d0 + d1 * d1 + d2 * d2 + d3 * d3;
#pragma unroll
    for (int o = 16; o > 0; o >>= 1) ss += __shfl_xor_sync(0xffffffffu, ss, o);
    if ((t & 31) == 0) r2[t >> 5] = ss;
    __syncthreads();
    float var = (r2[0] + r2[1] + r2[2] + r2[3]) * (1.0f / 511.0f);
    float rstd = rsqrtf(var);
    float4 gg = *(const float4*)&g[base];
    float4 bb = *(const float4*)&be[base];
    float4 o4;
    o4.x = fmaf(gg.x * rstd, d0, bb.x);
    o4.y = fmaf(gg.y * rstd, d1, bb.y);
    o4.z = fmaf(gg.z * rstd, d2, bb.z);
    o4.w = fmaf(gg.w * rstd, d3, bb.w);
    *(float4*)&out[base] = o4;
}

// ---------------- orchestration ----------------
extern "C" void kernel_launch(void* const* d_in, const int* in_sizes, int n_in,
                              void* d_out, int out_size) {
    const int* ids = (const int*)d_in[0];
    const float* E = (const float*)d_in[1];
    const float* WQ = (const float*)d_in[2];
    const float* WK = (const float*)d_in[3];
    const float* WV = (const float*)d_in[4];
    const float* WO = (const float*)d_in[5];
    const float* ln1g = (const float*)d_in[6];
    const float* ln1b = (const float*)d_in[7];
    const float* W1 = (const float*)d_in[8];
    const float* b1 = (const float*)d_in[9];
    const float* W2 = (const float*)d_in[10];
    const float* b2 = (const float*)d_in[11];
    const float* ln2g = (const float*)d_in[12];
    const float* ln2b = (const float*)d_in[13];
    float* out = (float*)d_out;
    (void)in_sizes; (void)n_in; (void)out_size;

    float *X, *Q, *Kb, *Vb, *S, *lse, *corr, *Acat, *Z, *F, *P;
    float2* part;
    cudaGetSymbolAddress((void**)&X, g_X);
    cudaGetSymbolAddress((void**)&Q, g_Q);
    cudaGetSymbolAddress((void**)&Kb, g_Kb);
    cudaGetSymbolAddress((void**)&Vb, g_Vb);
    cudaGetSymbolAddress((void**)&S, g_S);
    cudaGetSymbolAddress((void**)&part, g_part);
    cudaGetSymbolAddress((void**)&lse, g_lse);
    cudaGetSymbolAddress((void**)&corr, g_corr);
    cudaGetSymbolAddress((void**)&Acat, g_A);
    cudaGetSymbolAddress((void**)&Z, g_Z);
    cudaGetSymbolAddress((void**)&F, g_F);
    cudaGetSymbolAddress((void**)&P, g_P);

    embed_pe<<<NTOK, 128>>>(ids, E, X);

    const int redThreads = 256;
    for (int l = 0; l < NLAYER; l++) {
        const float* WQl = WQ + (size_t)l * NH * DMODEL * DHEAD;
        const float* WKl = WK + (size_t)l * NH * DMODEL * DHEAD;
        const float* WVl = WV + (size_t)l * NH * DMODEL * DHEAD;
        const float* WOl = WO + (size_t)l * DMODEL * DMODEL;
        const float* W1l = W1 + (size_t)l * DMODEL * DFFN;
        const float* b1l = b1 + (size_t)l * DFFN;
        const float* W2l = W2 + (size_t)l * DFFN * DMODEL;
        const float* b2l = b2 + (size_t)l * DMODEL;
        size_t lnOff = (size_t)l * NTOK * DMODEL;

        // ---- QKV projections (batched over heads, split-K x2) ----
        {
            dim3 gq(2, 32, 8);   // (splits*nTilesX=2, M/64, H)
            int rb = (NH * NTOK * 64 / 4 + redThreads - 1) / redThreads;
            sgemm_nn<64, 4><<<gq, 256>>>(X, WQl, nullptr, P, NTOK, 64, DMODEL,
                                         DMODEL, 64, 0, 0LL, 32768LL, 0LL,
                                         nullptr, 0, nullptr, 0, 0LL, 0, 1, 2);
            reduce_split<<<rb, redThreads>>>(P, Q, NTOK, 64, DMODEL, 64LL, 2,
                                             nullptr, 0, nullptr, 0, 0LL, 0, NH);
            sgemm_nn<64, 4><<<gq, 256>>>(X, WKl, nullptr, P, NTOK, 64, DMODEL,
                                         DMODEL, 64, 0, 0LL, 32768LL, 0LL,
                                         nullptr, 0, nullptr, 0, 0LL, 0, 1, 2);
            reduce_split<<<rb, redThreads>>>(P, Kb, NTOK, 64, DMODEL, 64LL, 2,
                                             nullptr, 0, nullptr, 0, 0LL, 0, NH);
            sgemm_nn<64, 4><<<gq, 256>>>(X, WVl, nullptr, P, NTOK, 64, DMODEL,
                                         DMODEL, 64, 0, 0LL, 32768LL, 0LL,
                                         nullptr, 0, nullptr, 0, 0LL, 0, 1, 2);
            reduce_split<<<rb, redThreads>>>(P, Vb, NTOK, 64, DMODEL, 64LL, 2,
                                             nullptr, 0, nullptr, 0, 0LL, 0, NH);
        }

        // ---- S = Q K^T / sqrt(DK) ----
        sgemm_nt_qk<<<dim3(32, 16, 8), 256>>>(Q, Kb, S, 0.125f);

        // ---- column logsumexp over q, per (h,m) ----
        lse_part_kernel<<<dim3(8, 8, 8), 256>>>(S, part);
        lse_combine_kernel<<<dim3(8, 8), 256>>>(part, lse);
        corr_kernel<<<NH, 256>>>(lse, Vb, corr);

        // ---- attn = S @ V - lse^T V  (split-K x4, corr as negated bias) ----
        sgemm_nn<64, 4><<<dim3(4, 32, 8), 256>>>(S, Vb, nullptr, P, NTOK, 64, NTOK,
                                                 NTOK, DMODEL, 0,
                                                 (long long)NTOK * NTOK, 64LL, 0LL,
                                                 nullptr, 0, nullptr, 0, 0LL, 0, 1, 4);
        {
            int rb = (NH * NTOK * 64 / 4 + redThreads - 1) / redThreads;
            reduce_split<<<rb, redThreads>>>(P, Acat, NTOK, 64, DMODEL, 64LL, 4,
                                             corr, 64, nullptr, 0, 0LL, 0, NH);
        }

        // ---- WO projection + residual (split-K x2) ----
        sgemm_nn<64, 4><<<dim3(16, 32, 1), 256>>>(Acat, WOl, nullptr, P, NTOK, DMODEL, DMODEL,
                                                  DMODEL, DMODEL, 0, 0LL, 0LL, 0LL,
                                                  nullptr, 0, nullptr, 0, 0LL, 0, 8, 2);
        {
            int rb = (NTOK * DMODEL / 4 + redThreads - 1) / redThreads;
            reduce_split<<<rb, redThreads>>>(P, Z, NTOK, DMODEL, DMODEL, 0LL, 2,
                                             nullptr, 0, X, DMODEL, 0LL, 0, 1);
        }
        layernorm_kernel<<<NTOK, 128>>>(Z, ln1g + lnOff, ln1b + lnOff, Z);

        // ---- FFN1: relu(Z @ W1 + b1) ----
        sgemm_nn<128, 8><<<dim3(32, 16, 1), 256>>>(Z, W1l, F, P, NTOK, DFFN, DMODEL,
                                                   DMODEL, DFFN, DFFN, 0LL, 0LL, 0LL,
                                                   b1l, 0, nullptr, 0, 0LL, 1, 32, 1);

        // ---- FFN2 + b2 + residual Z (split-K x4) ----
        sgemm_nn<64, 4><<<dim3(32, 32, 1), 256>>>(F, W2l, nullptr, P, NTOK, DMODEL, DFFN,
                                                  DFFN, DMODEL, 0, 0LL, 0LL, 0LL,
                                                  nullptr, 0, nullptr, 0, 0LL, 0, 8, 4);
        {
            int rb = (NTOK * DMODEL / 4 + redThreads - 1) / redThreads;
            reduce_split<<<rb, redThreads>>>(P, X, NTOK, DMODEL, DMODEL, 0LL, 4,
                                             b2l, 0, Z, DMODEL, 0LL, 0, 1);
        }
        layernorm_kernel<<<NTOK, 128>>>(X, ln2g + lnOff, ln2b + lnOff,
                                        (l == NLAYER - 1) ? out : X);
    }
}

// round 5
// speedup vs baseline: 2.0321x; 2.0321x over previous
#include <cuda_runtime.h>
#include <cstdint>

#define NTOK   2048
#define DMODEL 512
#define DFFN   2048
#define NH     8
#define DHEAD  64
#define NLAYER 6

// ---------------- device scratch (static, no allocation) ----------------
__device__ float g_X[NTOK * DMODEL];
__device__ float g_Q[NTOK * DMODEL];
__device__ float g_Kb[NTOK * DMODEL];
__device__ float g_Vb[NTOK * DMODEL];
__device__ float g_S[(size_t)NH * NTOK * NTOK];          // 128 MB
__device__ float2 g_part[NH * 8 * NTOK];
__device__ float g_lse[NH * NTOK];
__device__ float g_corr[NH * DHEAD];
__device__ float g_A[NTOK * DMODEL];
__device__ float g_Z[NTOK * DMODEL];
__device__ float g_F[NTOK * DFFN];

// ---------------- fast exp (FMA-only, no MUFU) ----------------
__device__ __forceinline__ float fexp(float x) {
    x = fmaxf(x, -87.0f);
    float t = x * 1.4426950408889634f;
    const float big = 12582912.0f;
    float r = __fadd_rn(t, big) - big;
    float f = t - r;
    float p = 1.5403530e-4f;
    p = fmaf(p, f, 1.33335581e-3f);
    p = fmaf(p, f, 9.61812911e-3f);
    p = fmaf(p, f, 5.55041087e-2f);
    p = fmaf(p, f, 2.40226507e-1f);
    p = fmaf(p, f, 6.93147181e-1f);
    p = fmaf(p, f, 1.0f);
    int e = (int)r;
    return p * __int_as_float((e + 127) << 23);
}

// ---------------- tf32 / mma helpers ----------------
__device__ __forceinline__ uint32_t f2tf(float x) {
    uint32_t r;
    asm("cvt.rna.tf32.f32 %0, %1;" : "=r"(r) : "f"(x));
    return r;
}
__device__ __forceinline__ void ldsm4(uint32_t r[4], uint32_t addr) {
    asm volatile("ldmatrix.sync.aligned.m8n8.x4.shared.b16 {%0,%1,%2,%3}, [%4];"
                 : "=r"(r[0]), "=r"(r[1]), "=r"(r[2]), "=r"(r[3]) : "r"(addr));
}
__device__ __forceinline__ void mma_tf32(float d[4], const uint32_t a[4],
                                         uint32_t b0, uint32_t b1) {
    asm volatile(
        "mma.sync.aligned.m16n8k8.row.col.f32.tf32.tf32.f32 "
        "{%0,%1,%2,%3}, {%4,%5,%6,%7}, {%8,%9}, {%0,%1,%2,%3};"
        : "+f"(d[0]), "+f"(d[1]), "+f"(d[2]), "+f"(d[3])
        : "r"(a[0]), "r"(a[1]), "r"(a[2]), "r"(a[3]), "r"(b0), "r"(b1));
}

// ---------------- embedding + positional encoding ----------------
__global__ void embed_pe(const int* __restrict__ ids, const float* __restrict__ E,
                         float* __restrict__ X) {
    int n = blockIdx.x, t = threadIdx.x;                  // 128 threads
    int id = ids[n];
    float4 e = *(const float4*)&E[(size_t)id * DMODEL + t * 4];
    float ev[4] = {e.x, e.y, e.z, e.w};
    float pos = (float)(n + 1);
    float ov[4];
#pragma unroll
    for (int i = 0; i < 4; i++) {
        int d = t * 4 + i;
        int de = d & ~1;
        float f = expf((float)de * (-9.210340371976184f / 512.0f));
        float arg = pos * f;
        float pe = (d & 1) ? cosf(arg) : sinf(arg);
        ov[i] = ev[i] + pe;
    }
    *(float4*)&X[(size_t)n * DMODEL + t * 4] = *(float4*)ov;
}

// ---------------- TF32 tensor-core GEMM ----------------
// C = alpha * A(MxK) * B + bias + res, optional relu.
// TRANSB=false: B is KxN row-major (NN).  TRANSB=true: B is NxK row-major (NT).
// Tile: BM=128, BN=64, BK=32. 256 threads = 8 warps; warp tile 32x32.
// Smem K-major rows with XOR-16B-chunk swizzle; ldmatrix b16 trick feeds
// exact m16n8k8 tf32 fragment layouts for both A and B.
template <bool TRANSB, bool RELU>
__global__ void __launch_bounds__(256)
gemm_tc(const float* __restrict__ Ag, const float* __restrict__ Bg,
        float* __restrict__ Cg, int K, int lda, int ldb, int ldc,
        long long sA, long long sB, long long sC,
        const float* __restrict__ biasg, int sBias,
        const float* __restrict__ resg, int ldr, long long sR,
        float alpha) {
    __shared__ __align__(16) float As[128 * 32];
    __shared__ __align__(16) float Bs[64 * 32];

    const int tid = threadIdx.x;
    const int bz = blockIdx.z;
    const float* A = Ag + (size_t)bz * sA + (size_t)blockIdx.y * 128 * lda;
    const float* B = TRANSB
        ? Bg + (size_t)bz * sB + (size_t)blockIdx.x * 64 * ldb
        : Bg + (size_t)bz * sB + (size_t)blockIdx.x * 64;

    const int ar = tid >> 3, ac = tid & 7;     // row-group / 16B-chunk loader coords
    const int kk_ld = tid >> 4, ng_ld = tid & 15;  // NN-B loader coords

    float4 aR[4], bR[2];

    auto ldgA = [&](int k0) {
#pragma unroll
        for (int i = 0; i < 4; i++)
            aR[i] = *(const float4*)&A[(size_t)(ar + i * 32) * lda + k0 + ac * 4];
    };
    auto ldgB = [&](int k0) {
        if (TRANSB) {
#pragma unroll
            for (int i = 0; i < 2; i++)
                bR[i] = *(const float4*)&B[(size_t)(ar + i * 32) * ldb + k0 + ac * 4];
        } else {
#pragma unroll
            for (int i = 0; i < 2; i++)
                bR[i] = *(const float4*)&B[(size_t)(k0 + kk_ld + i * 16) * ldb + ng_ld * 4];
        }
    };
    auto stsA = [&]() {
        uint32_t* Asu = (uint32_t*)As;
#pragma unroll
        for (int i = 0; i < 4; i++) {
            int r = ar + i * 32;
            int base = r * 32 + ((ac ^ (r & 7)) << 2);
            Asu[base + 0] = f2tf(aR[i].x);
            Asu[base + 1] = f2tf(aR[i].y);
            Asu[base + 2] = f2tf(aR[i].z);
            Asu[base + 3] = f2tf(aR[i].w);
        }
    };
    auto stsB = [&]() {
        uint32_t* Bsu = (uint32_t*)Bs;
        if (TRANSB) {
#pragma unroll
            for (int i = 0; i < 2; i++) {
                int r = ar + i * 32;
                int base = r * 32 + ((ac ^ (r & 7)) << 2);
                Bsu[base + 0] = f2tf(bR[i].x);
                Bsu[base + 1] = f2tf(bR[i].y);
                Bsu[base + 2] = f2tf(bR[i].z);
                Bsu[base + 3] = f2tf(bR[i].w);
            }
        } else {
#pragma unroll
            for (int i = 0; i < 2; i++) {
                int k = kk_ld + i * 16;
                float v[4] = {bR[i].x, bR[i].y, bR[i].z, bR[i].w};
#pragma unroll
                for (int j = 0; j < 4; j++) {
                    int n = ng_ld * 4 + j;
                    Bsu[n * 32 + (((k >> 2) ^ (n & 7)) << 2) + (k & 3)] = f2tf(v[j]);
                }
            }
        }
    };

    const int lane = tid & 31, warp = tid >> 5;
    const int wm = (warp & 3) << 5, wn = (warp >> 2) << 5;
    // ldmatrix address generators
    const int arow = wm + (lane & 7) + ((lane >> 3) & 1) * 8;   // +mb*16
    const int ahi = lane >> 4;
    const int r7a = arow & 7;
    const int brow = wn + (lane & 7) + ((lane >> 4) & 1) * 8;   // +g*16
    const int bhi = (lane >> 3) & 1;
    const int r7b = brow & 7;
    uint32_t As_u = (uint32_t)__cvta_generic_to_shared(As);
    uint32_t Bs_u = (uint32_t)__cvta_generic_to_shared(Bs);

    float d[2][4][4];
#pragma unroll
    for (int i = 0; i < 2; i++)
#pragma unroll
        for (int j = 0; j < 4; j++)
#pragma unroll
            for (int q = 0; q < 4; q++) d[i][j][q] = 0.f;

    ldgA(0); ldgB(0);
    stsA(); stsB();
    __syncthreads();

    const int nkt = K >> 5;
    for (int kt = 0; kt < nkt; kt++) {
        if (kt + 1 < nkt) { ldgA((kt + 1) << 5); ldgB((kt + 1) << 5); }
#pragma unroll
        for (int ks = 0; ks < 4; ks++) {
            uint32_t afr[2][4], bfr[2][4];
            int ca = ((2 * ks + ahi) ^ r7a) << 4;
            int cb = ((2 * ks + bhi) ^ r7b) << 4;
            ldsm4(afr[0], As_u + (uint32_t)(arow * 128) + ca);
            ldsm4(afr[1], As_u + (uint32_t)((arow + 16) * 128) + ca);
            ldsm4(bfr[0], Bs_u + (uint32_t)(brow * 128) + cb);
            ldsm4(bfr[1], Bs_u + (uint32_t)((brow + 16) * 128) + cb);
#pragma unroll
            for (int mb = 0; mb < 2; mb++)
#pragma unroll
                for (int nb = 0; nb < 4; nb++)
                    mma_tf32(d[mb][nb], afr[mb],
                             bfr[nb >> 1][(nb & 1) * 2], bfr[nb >> 1][(nb & 1) * 2 + 1]);
        }
        __syncthreads();
        if (kt + 1 < nkt) { stsA(); stsB(); __syncthreads(); }
    }

    // epilogue
    const int gr = lane >> 2, gc = (lane & 3) * 2;
    const int mBase = blockIdx.y * 128 + wm;
    const int nBase = blockIdx.x * 64 + wn;
    float* C = Cg + (size_t)bz * sC;
    const float* bi = biasg ? biasg + (size_t)bz * sBias : nullptr;
    const float* Rg = resg ? resg + (size_t)bz * sR : nullptr;
#pragma unroll
    for (int mb = 0; mb < 2; mb++)
#pragma unroll
        for (int nb = 0; nb < 4; nb++)
#pragma unroll
            for (int h2 = 0; h2 < 2; h2++) {
                int m = mBase + mb * 16 + gr + h2 * 8;
                int n = nBase + nb * 8 + gc;
                float v0 = d[mb][nb][h2 * 2] * alpha;
                float v1 = d[mb][nb][h2 * 2 + 1] * alpha;
                if (bi) {
                    float2 bb = *(const float2*)&bi[n];
                    v0 += bb.x; v1 += bb.y;
                }
                if (Rg) {
                    float2 rr = *(const float2*)&Rg[(size_t)m * ldr + n];
                    v0 += rr.x; v1 += rr.y;
                }
                if (RELU) { v0 = fmaxf(v0, 0.f); v1 = fmaxf(v1, 0.f); }
                *(float2*)&C[(size_t)m * ldc + n] = make_float2(v0, v1);
            }
}

// ---------------- column-wise logsumexp over query axis (segmented) ----------------
__global__ void lse_part_kernel(const float* __restrict__ S, float2* __restrict__ part) {
    int m = blockIdx.x * 256 + threadIdx.x;
    int seg = blockIdx.y;
    int h = blockIdx.z;
    const float* col = S + (size_t)h * NTOK * NTOK + (size_t)seg * (NTOK / 8) * NTOK + m;
    float mx = -3.0e38f, s = 0.f;
#pragma unroll 4
    for (int q = 0; q < NTOK / 8; q++) {
        float x = col[(size_t)q * NTOK];
        float nm = fmaxf(mx, x);
        s = fmaf(s, fexp(mx - nm), fexp(x - nm));
        mx = nm;
    }
    part[((size_t)h * 8 + seg) * NTOK + m] = make_float2(mx, s);
}

__global__ void lse_combine_kernel(const float2* __restrict__ part, float* __restrict__ lse) {
    int m = blockIdx.x * 256 + threadIdx.x;
    int h = blockIdx.y;
    float2 p[8];
    float mx = -3.0e38f;
#pragma unroll
    for (int s = 0; s < 8; s++) {
        p[s] = part[((size_t)h * 8 + s) * NTOK + m];
        mx = fmaxf(mx, p[s].x);
    }
    float sum = 0.f;
#pragma unroll
    for (int s = 0; s < 8; s++) sum += p[s].y * expf(p[s].x - mx);
    lse[h * NTOK + m] = mx + logf(sum);
}

// corr[h][v] = -sum_m lse[h,m] * V[m, h*64+v]
__global__ void corr_kernel(const float* __restrict__ lse, const float* __restrict__ Vb,
                            float* __restrict__ corr) {
    int h = blockIdx.x, t = threadIdx.x;
    int v = t & 63, seg = t >> 6;
    const float* Vp = Vb + h * 64 + v;
    const float* lp = lse + h * NTOK;
    float acc = 0.f;
    for (int m = seg * 512; m < seg * 512 + 512; m++)
        acc = fmaf(lp[m], Vp[(size_t)m * 512], acc);
    __shared__ float red[256];
    red[t] = acc;
    __syncthreads();
    if (t < 64) {
        float tot = red[t] + red[t + 64] + red[t + 128] + red[t + 192];
        corr[h * 64 + t] = -tot;
    }
}

// ---------------- layernorm (ddof=1, no eps, elementwise gain/bias) ----------------
__global__ void layernorm_kernel(const float* __restrict__ in, const float* __restrict__ g,
                                 const float* __restrict__ be, float* __restrict__ out) {
    int n = blockIdx.x, t = threadIdx.x;                   // 128 threads
    size_t base = (size_t)n * 512 + t * 4;
    float4 x = *(const float4*)&in[base];
    float s = x.x + x.y + x.z + x.w;
#pragma unroll
    for (int o = 16; o > 0; o >>= 1) s += __shfl_xor_sync(0xffffffffu, s, o);
    __shared__ float r1[4], r2[4];
    if ((t & 31) == 0) r1[t >> 5] = s;
    __syncthreads();
    float mean = (r1[0] + r1[1] + r1[2] + r1[3]) * (1.0f / 512.0f);
    float d0 = x.x - mean, d1 = x.y - mean, d2 = x.z - mean, d3 = x.w - mean;
    float ss = d0 * d0 + d1 * d1 + d2 * d2 + d3 * d3;
#pragma unroll
    for (int o = 16; o > 0; o >>= 1) ss += __shfl_xor_sync(0xffffffffu, ss, o);
    if ((t & 31) == 0) r2[t >> 5] = ss;
    __syncthreads();
    float var = (r2[0] + r2[1] + r2[2] + r2[3]) * (1.0f / 511.0f);
    float rstd = rsqrtf(var);
    float4 gg = *(const float4*)&g[base];
    float4 bb = *(const float4*)&be[base];
    float4 o4;
    o4.x = fmaf(gg.x * rstd, d0, bb.x);
    o4.y = fmaf(gg.y * rstd, d1, bb.y);
    o4.z = fmaf(gg.z * rstd, d2, bb.z);
    o4.w = fmaf(gg.w * rstd, d3, bb.w);
    *(float4*)&out[base] = o4;
}

// ---------------- orchestration ----------------
extern "C" void kernel_launch(void* const* d_in, const int* in_sizes, int n_in,
                              void* d_out, int out_size) {
    const int* ids = (const int*)d_in[0];
    const float* E = (const float*)d_in[1];
    const float* WQ = (const float*)d_in[2];
    const float* WK = (const float*)d_in[3];
    const float* WV = (const float*)d_in[4];
    const float* WO = (const float*)d_in[5];
    const float* ln1g = (const float*)d_in[6];
    const float* ln1b = (const float*)d_in[7];
    const float* W1 = (const float*)d_in[8];
    const float* b1 = (const float*)d_in[9];
    const float* W2 = (const float*)d_in[10];
    const float* b2 = (const float*)d_in[11];
    const float* ln2g = (const float*)d_in[12];
    const float* ln2b = (const float*)d_in[13];
    float* out = (float*)d_out;
    (void)in_sizes; (void)n_in; (void)out_size;

    float *X, *Q, *Kb, *Vb, *S, *lse, *corr, *Acat, *Z, *F;
    float2* part;
    cudaGetSymbolAddress((void**)&X, g_X);
    cudaGetSymbolAddress((void**)&Q, g_Q);
    cudaGetSymbolAddress((void**)&Kb, g_Kb);
    cudaGetSymbolAddress((void**)&Vb, g_Vb);
    cudaGetSymbolAddress((void**)&S, g_S);
    cudaGetSymbolAddress((void**)&part, g_part);
    cudaGetSymbolAddress((void**)&lse, g_lse);
    cudaGetSymbolAddress((void**)&corr, g_corr);
    cudaGetSymbolAddress((void**)&Acat, g_A);
    cudaGetSymbolAddress((void**)&Z, g_Z);
    cudaGetSymbolAddress((void**)&F, g_F);

    embed_pe<<<NTOK, 128>>>(ids, E, X);

    const long long SNN = (long long)NTOK * NTOK;

    for (int l = 0; l < NLAYER; l++) {
        const float* WQl = WQ + (size_t)l * NH * DMODEL * DHEAD;
        const float* WKl = WK + (size_t)l * NH * DMODEL * DHEAD;
        const float* WVl = WV + (size_t)l * NH * DMODEL * DHEAD;
        const float* WOl = WO + (size_t)l * DMODEL * DMODEL;
        const float* W1l = W1 + (size_t)l * DMODEL * DFFN;
        const float* b1l = b1 + (size_t)l * DFFN;
        const float* W2l = W2 + (size_t)l * DFFN * DMODEL;
        const float* b2l = b2 + (size_t)l * DMODEL;
        size_t lnOff = (size_t)l * NTOK * DMODEL;

        // ---- QKV projections (batched over heads) ----
        gemm_tc<false, false><<<dim3(1, 16, 8), 256>>>(
            X, WQl, Q, DMODEL, DMODEL, DHEAD, DMODEL,
            0LL, (long long)DMODEL * DHEAD, 64LL,
            nullptr, 0, nullptr, 0, 0LL, 1.0f);
        gemm_tc<false, false><<<dim3(1, 16, 8), 256>>>(
            X, WKl, Kb, DMODEL, DMODEL, DHEAD, DMODEL,
            0LL, (long long)DMODEL * DHEAD, 64LL,
            nullptr, 0, nullptr, 0, 0LL, 1.0f);
        gemm_tc<false, false><<<dim3(1, 16, 8), 256>>>(
            X, WVl, Vb, DMODEL, DMODEL, DHEAD, DMODEL,
            0LL, (long long)DMODEL * DHEAD, 64LL,
            nullptr, 0, nullptr, 0, 0LL, 1.0f);

        // ---- S = Q K^T / sqrt(DK) ----
        gemm_tc<true, false><<<dim3(32, 16, 8), 256>>>(
            Q, Kb, S, DHEAD, DMODEL, DMODEL, NTOK,
            64LL, 64LL, SNN,
            nullptr, 0, nullptr, 0, 0LL, 0.125f);

        // ---- column logsumexp over q, per (h,m) ----
        lse_part_kernel<<<dim3(8, 8, 8), 256>>>(S, part);
        lse_combine_kernel<<<dim3(8, 8), 256>>>(part, lse);
        corr_kernel<<<NH, 256>>>(lse, Vb, corr);

        // ---- attn = S @ V + corr (corr = -lse^T V, rank-1 softmax correction) ----
        gemm_tc<false, false><<<dim3(1, 16, 8), 256>>>(
            S, Vb, Acat, NTOK, NTOK, DMODEL, DMODEL,
            SNN, 64LL, 64LL,
            corr, 64, nullptr, 0, 0LL, 1.0f);

        // ---- Z = Acat @ WO + X ----
        gemm_tc<false, false><<<dim3(8, 16, 1), 256>>>(
            Acat, WOl, Z, DMODEL, DMODEL, DMODEL, DMODEL,
            0LL, 0LL, 0LL,
            nullptr, 0, X, DMODEL, 0LL, 1.0f);
        layernorm_kernel<<<NTOK, 128>>>(Z, ln1g + lnOff, ln1b + lnOff, Z);

        // ---- F = relu(Z @ W1 + b1) ----
        gemm_tc<false, true><<<dim3(32, 16, 1), 256>>>(
            Z, W1l, F, DMODEL, DMODEL, DFFN, DFFN,
            0LL, 0LL, 0LL,
            b1l, 0, nullptr, 0, 0LL, 1.0f);

        // ---- X = F @ W2 + b2 + Z ----
        gemm_tc<false, false><<<dim3(8, 16, 1), 256>>>(
            F, W2l, X, DFFN, DFFN, DMODEL, DMODEL,
            0LL, 0LL, 0LL,
            b2l, 0, Z, DMODEL, 0LL, 1.0f);
        layernorm_kernel<<<NTOK, 128>>>(X, ln2g + lnOff, ln2b + lnOff,
                                        (l == NLAYER - 1) ? out : X);
    }
}

// round 6
// speedup vs baseline: 2.2124x; 1.0888x over previous
#include <cuda_runtime.h>
#include <cstdint>

#define NTOK   2048
#define DMODEL 512
#define DFFN   2048
#define NH     8
#define DHEAD  64
#define NLAYER 6

// ---------------- device scratch (static, no allocation) ----------------
__device__ float g_X[NTOK * DMODEL];
__device__ float g_QKV[3 * NTOK * DMODEL];               // Q | K | V planes
__device__ float g_S[(size_t)NH * NTOK * NTOK];          // 128 MB
__device__ float2 g_part[NH * 8 * NTOK];
__device__ float g_lse[NH * NTOK];
__device__ float g_corr[NH * DHEAD];
__device__ float g_A[NTOK * DMODEL];
__device__ float g_Z[NTOK * DMODEL];
__device__ float g_F[NTOK * DFFN];
__device__ float g_P[4 * NTOK * DMODEL];                 // split-K partials (16 MB)

// ---------------- fast exp (FMA-only, no MUFU) ----------------
__device__ __forceinline__ float fexp(float x) {
    x = fmaxf(x, -87.0f);
    float t = x * 1.4426950408889634f;
    const float big = 12582912.0f;
    float r = __fadd_rn(t, big) - big;
    float f = t - r;
    float p = 1.5403530e-4f;
    p = fmaf(p, f, 1.33335581e-3f);
    p = fmaf(p, f, 9.61812911e-3f);
    p = fmaf(p, f, 5.55041087e-2f);
    p = fmaf(p, f, 2.40226507e-1f);
    p = fmaf(p, f, 6.93147181e-1f);
    p = fmaf(p, f, 1.0f);
    int e = (int)r;
    return p * __int_as_float((e + 127) << 23);
}

// ---------------- bf16 / mma helpers ----------------
__device__ __forceinline__ uint32_t packbf(float e0, float e1) {  // e0 -> bits[15:0]
    uint32_t r;
    asm("cvt.rn.bf16x2.f32 %0, %1, %2;" : "=r"(r) : "f"(e1), "f"(e0));
    return r;
}
__device__ __forceinline__ float lo_f(uint32_t p) { return __uint_as_float(p << 16); }
__device__ __forceinline__ float hi_f(uint32_t p) { return __uint_as_float(p & 0xffff0000u); }

__device__ __forceinline__ void cvt_store4(char* hiP, char* loP, float4 v) {
    uint32_t h01 = packbf(v.x, v.y), h23 = packbf(v.z, v.w);
    uint32_t l01 = packbf(v.x - lo_f(h01), v.y - hi_f(h01));
    uint32_t l23 = packbf(v.z - lo_f(h23), v.w - hi_f(h23));
    *(uint2*)hiP = make_uint2(h01, h23);
    *(uint2*)loP = make_uint2(l01, l23);
}

__device__ __forceinline__ void ldsm4(uint32_t r[4], uint32_t addr) {
    asm volatile("ldmatrix.sync.aligned.m8n8.x4.shared.b16 {%0,%1,%2,%3}, [%4];"
                 : "=r"(r[0]), "=r"(r[1]), "=r"(r[2]), "=r"(r[3]) : "r"(addr));
}
__device__ __forceinline__ void ldsm4t(uint32_t r[4], uint32_t addr) {
    asm volatile("ldmatrix.sync.aligned.m8n8.x4.trans.shared.b16 {%0,%1,%2,%3}, [%4];"
                 : "=r"(r[0]), "=r"(r[1]), "=r"(r[2]), "=r"(r[3]) : "r"(addr));
}
__device__ __forceinline__ void mma_bf16(float d[4], const uint32_t a[4],
                                         uint32_t b0, uint32_t b1) {
    asm volatile(
        "mma.sync.aligned.m16n8k16.row.col.f32.bf16.bf16.f32 "
        "{%0,%1,%2,%3}, {%4,%5,%6,%7}, {%8,%9}, {%0,%1,%2,%3};"
        : "+f"(d[0]), "+f"(d[1]), "+f"(d[2]), "+f"(d[3])
        : "r"(a[0]), "r"(a[1]), "r"(a[2]), "r"(a[3]), "r"(b0), "r"(b1));
}

// ---------------- embedding + positional encoding ----------------
__global__ void embed_pe(const int* __restrict__ ids, const float* __restrict__ E,
                         float* __restrict__ X) {
    int n = blockIdx.x, t = threadIdx.x;                  // 128 threads
    int id = ids[n];
    float4 e = *(const float4*)&E[(size_t)id * DMODEL + t * 4];
    float ev[4] = {e.x, e.y, e.z, e.w};
    float pos = (float)(n + 1);
    float ov[4];
#pragma unroll
    for (int i = 0; i < 4; i++) {
        int d = t * 4 + i;
        int de = d & ~1;
        float f = expf((float)de * (-9.210340371976184f / 512.0f));
        float arg = pos * f;
        float pe = (d & 1) ? cosf(arg) : sinf(arg);
        ov[i] = ev[i] + pe;
    }
    *(float4*)&X[(size_t)n * DMODEL + t * 4] = *(float4*)ov;
}

// ---------------- bf16x3 tensor-core GEMM (fp32-grade accuracy) ----------------
// C = alpha*A*B + bias + res, optional relu; or raw partials to Pbuf (split-K).
// TRANSB=false: B is KxN row-major.  TRANSB=true: B is NxK row-major.
// BM=128, BN=64, BK=32; 256 threads / 8 warps; warp tile 32x32.
// A and B each split into bf16 hi+lo planes; 3 MMAs per fragment pair.
template <bool TRANSB, bool RELU, bool QKV, bool SPLITK>
__global__ void __launch_bounds__(256, 2)
gemm_tc(const float* __restrict__ Ag, const float* __restrict__ Bg,
        float* __restrict__ Cg, int K, int lda, int ldb, int ldc,
        long long sA, long long sB, long long sC,
        const float* __restrict__ biasg, int sBias,
        const float* __restrict__ resg, int ldr, long long sR,
        float alpha,
        const float* __restrict__ Bg1, const float* __restrict__ Bg2,
        float* __restrict__ Pbuf, int nsplit, int zInner) {
    constexpr int BPLANE = TRANSB ? 5120 : 4096;          // B smem plane bytes
    __shared__ __align__(16) char sm[20480 + 2 * BPLANE]; // A: 2x10240
    char* Ahi = sm;
    char* Alo = sm + 10240;
    char* Bhi = sm + 20480;
    char* Blo = sm + 20480 + BPLANE;

    const int tid = threadIdx.x;
    const int bz = blockIdx.z;
    int bzIn = bz, split = 0;
    if (SPLITK) { bzIn = bz % zInner; split = bz / zInner; }
    const int kLen = SPLITK ? K / nsplit : K;
    const int kStart = SPLITK ? split * kLen : 0;

    const float* A = Ag + (size_t)bzIn * sA + (size_t)blockIdx.y * 128 * lda + kStart;
    const float* B;
    if (QKV) {
        int op = bz >> 3;
        const float* Bsel = (op == 0) ? Bg : (op == 1 ? Bg1 : Bg2);
        B = Bsel + (size_t)(bz & 7) * sB;
    } else if (TRANSB) {
        B = Bg + (size_t)bzIn * sB + (size_t)blockIdx.x * 64 * ldb + kStart;
    } else {
        B = Bg + (size_t)bzIn * sB + (size_t)kStart * ldb + (size_t)blockIdx.x * 64;
    }

    const int ar = tid >> 3, ac = tid & 7;                // A/B-NT loader coords
    const int kk_ld = tid >> 4, nb4 = (tid & 15) * 4;     // B-NN loader coords

    float4 aR[4], bR[2];

    auto ldgA = [&](int k0) {
#pragma unroll
        for (int i = 0; i < 4; i++)
            aR[i] = *(const float4*)&A[(size_t)(ar + i * 32) * lda + k0 + ac * 4];
    };
    auto ldgB = [&](int k0) {
        if (TRANSB) {
#pragma unroll
            for (int i = 0; i < 2; i++)
                bR[i] = *(const float4*)&B[(size_t)(ar + i * 32) * ldb + k0 + ac * 4];
        } else {
#pragma unroll
            for (int i = 0; i < 2; i++)
                bR[i] = *(const float4*)&B[(size_t)(k0 + kk_ld + i * 16) * ldb + nb4];
        }
    };
    auto stsA = [&]() {
#pragma unroll
        for (int i = 0; i < 4; i++) {
            int off = (ar + i * 32) * 80 + ac * 8;        // 80B-pitch rows (conflict-free)
            cvt_store4(Ahi + off, Alo + off, aR[i]);
        }
    };
    auto stsB = [&]() {
        if (TRANSB) {
#pragma unroll
            for (int i = 0; i < 2; i++) {
                int off = (ar + i * 32) * 80 + ac * 8;
                cvt_store4(Bhi + off, Blo + off, bR[i]);
            }
        } else {
#pragma unroll
            for (int i = 0; i < 2; i++) {
                int k = kk_ld + i * 16;                   // [k][n] 128B rows, chunk^k swizzle
                int off = k * 128 + (((nb4 >> 3) ^ (k & 7)) << 4) + ((nb4 & 4) << 1);
                cvt_store4(Bhi + off, Blo + off, bR[i]);
            }
        }
    };

    const int lane = tid & 31, warp = tid >> 5;
    const int wm = (warp & 3) << 5, wn = (warp >> 2) << 5;
    uint32_t sm_u = (uint32_t)__cvta_generic_to_shared(sm);
    // A ldmatrix base: row = wm + (lane&15), 16B half by lane>>4
    const uint32_t aBase = sm_u + (uint32_t)((wm + (lane & 15)) * 80 + (lane >> 4) * 16);
    // B (TRANSB) same scheme on 80B rows
    const uint32_t bBaseT = sm_u + 20480u + (uint32_t)((wn + (lane & 15)) * 80 + (lane >> 4) * 16);
    // B (NN, trans-ldmatrix): k-row per lane + chunk column
    const int krowL = (lane & 7) + ((lane >> 4) << 3);
    const int chnkL = (wn >> 3) + ((lane >> 3) & 1);

    float d[2][4][4];
#pragma unroll
    for (int i = 0; i < 2; i++)
#pragma unroll
        for (int j = 0; j < 4; j++)
#pragma unroll
            for (int q = 0; q < 4; q++) d[i][j][q] = 0.f;

    ldgA(0); ldgB(0);
    stsA(); stsB();
    __syncthreads();

    const int nkt = kLen >> 5;
    for (int kt = 0; kt < nkt; kt++) {
        if (kt + 1 < nkt) { ldgA((kt + 1) << 5); ldgB((kt + 1) << 5); }
#pragma unroll
        for (int ks = 0; ks < 2; ks++) {
            uint32_t ah[2][4], al[2][4], bh[2][4], bl[2][4];
#pragma unroll
            for (int mb = 0; mb < 2; mb++) {
                uint32_t a = aBase + (uint32_t)(mb * 16 * 80 + ks * 32);
                ldsm4(ah[mb], a);
                ldsm4(al[mb], a + 10240u);
            }
#pragma unroll
            for (int g = 0; g < 2; g++) {
                if (TRANSB) {
                    uint32_t b = bBaseT + (uint32_t)(g * 16 * 80 + ks * 32);
                    ldsm4(bh[g], b);
                    ldsm4(bl[g], b + 5120u);
                } else {
                    int k = ks * 16 + krowL;
                    uint32_t b = sm_u + 20480u +
                                 (uint32_t)(k * 128 + (((chnkL + g * 2) ^ (k & 7)) << 4));
                    ldsm4t(bh[g], b);
                    ldsm4t(bl[g], b + 4096u);
                }
            }
#pragma unroll
            for (int mb = 0; mb < 2; mb++)
#pragma unroll
                for (int nb = 0; nb < 4; nb++) {
                    int g = nb >> 1, j = nb & 1;
                    uint32_t B0 = bh[g][j], B1 = bh[g][j + 2];
                    mma_bf16(d[mb][nb], ah[mb], B0, B1);
                    mma_bf16(d[mb][nb], ah[mb], bl[g][j], bl[g][j + 2]);
                    mma_bf16(d[mb][nb], al[mb], B0, B1);
                }
        }
        __syncthreads();
        if (kt + 1 < nkt) { stsA(); stsB(); __syncthreads(); }
    }

    // epilogue
    const int gr = lane >> 2, gc = (lane & 3) * 2;
    const int mBase = blockIdx.y * 128 + wm;
    const int nBase = blockIdx.x * 64 + wn;
    if (SPLITK) {
        const int Mfull = gridDim.y * 128, Nfull = gridDim.x * 64;
        float* P = Pbuf + (size_t)(split * zInner + bzIn) * Mfull * Nfull;
#pragma unroll
        for (int mb = 0; mb < 2; mb++)
#pragma unroll
            for (int nb = 0; nb < 4; nb++)
#pragma unroll
                for (int h2 = 0; h2 < 2; h2++) {
                    int m = mBase + mb * 16 + gr + h2 * 8;
                    int n = nBase + nb * 8 + gc;
                    *(float2*)&P[(size_t)m * Nfull + n] =
                        make_float2(d[mb][nb][h2 * 2] * alpha, d[mb][nb][h2 * 2 + 1] * alpha);
                }
        return;
    }
    float* C;
    if (QKV) {
        C = Cg + (size_t)(bz >> 3) * (NTOK * DMODEL) + (size_t)(bz & 7) * 64;
    } else {
        C = Cg + (size_t)bzIn * sC;
    }
    const float* bi = biasg ? biasg + (size_t)bzIn * sBias : nullptr;
    const float* Rg = resg ? resg + (size_t)bzIn * sR : nullptr;
#pragma unroll
    for (int mb = 0; mb < 2; mb++)
#pragma unroll
        for (int nb = 0; nb < 4; nb++)
#pragma unroll
            for (int h2 = 0; h2 < 2; h2++) {
                int m = mBase + mb * 16 + gr + h2 * 8;
                int n = nBase + nb * 8 + gc;
                float v0 = d[mb][nb][h2 * 2] * alpha;
                float v1 = d[mb][nb][h2 * 2 + 1] * alpha;
                if (bi) {
                    float2 bb = *(const float2*)&bi[n];
                    v0 += bb.x; v1 += bb.y;
                }
                if (Rg) {
                    float2 rr = *(const float2*)&Rg[(size_t)m * ldr + n];
                    v0 += rr.x; v1 += rr.y;
                }
                if (RELU) { v0 = fmaxf(v0, 0.f); v1 = fmaxf(v1, 0.f); }
                *(float2*)&C[(size_t)m * ldc + n] = make_float2(v0, v1);
            }
}

// ---------------- split-K reduction + epilogue (deterministic order) ----------------
__global__ void reduce_split(const float* __restrict__ P, float* __restrict__ C,
                             int M, int Nn, int ldc, long long sC, int nsplit,
                             const float* __restrict__ bias, int sBias,
                             const float* __restrict__ res, int ldr, long long sR,
                             int relu, int batch) {
    size_t perBatch = (size_t)M * Nn;
    size_t total4 = (size_t)batch * perBatch / 4;
    size_t idx = (size_t)blockIdx.x * blockDim.x + threadIdx.x;
    if (idx >= total4) return;
    size_t e4 = idx * 4;
    int b = (int)(e4 / perBatch);
    size_t r = e4 % perBatch;
    int m = (int)(r / Nn);
    int n = (int)(r % Nn);
    size_t splitStride = (size_t)batch * perBatch;
    float4 v = *(const float4*)&P[e4];
    for (int s = 1; s < nsplit; s++) {
        float4 p = *(const float4*)&P[(size_t)s * splitStride + e4];
        v.x += p.x; v.y += p.y; v.z += p.z; v.w += p.w;
    }
    if (bias) {
        const float* bi = bias + (size_t)b * sBias;
        v.x += bi[n]; v.y += bi[n + 1]; v.z += bi[n + 2]; v.w += bi[n + 3];
    }
    if (res) {
        float4 r4 = *(const float4*)&res[(size_t)b * sR + (size_t)m * ldr + n];
        v.x += r4.x; v.y += r4.y; v.z += r4.z; v.w += r4.w;
    }
    if (relu) {
        v.x = fmaxf(v.x, 0.f); v.y = fmaxf(v.y, 0.f);
        v.z = fmaxf(v.z, 0.f); v.w = fmaxf(v.w, 0.f);
    }
    *(float4*)&C[(size_t)b * sC + (size_t)m * ldc + n] = v;
}

// ---------------- column-wise logsumexp over query axis (segmented) ----------------
__global__ void lse_part_kernel(const float* __restrict__ S, float2* __restrict__ part) {
    int m = blockIdx.x * 256 + threadIdx.x;
    int seg = blockIdx.y;
    int h = blockIdx.z;
    const float* col = S + (size_t)h * NTOK * NTOK + (size_t)seg * (NTOK / 8) * NTOK + m;
    float mx = -3.0e38f, s = 0.f;
#pragma unroll 4
    for (int q = 0; q < NTOK / 8; q++) {
        float x = col[(size_t)q * NTOK];
        float nm = fmaxf(mx, x);
        s = fmaf(s, fexp(mx - nm), fexp(x - nm));
        mx = nm;
    }
    part[((size_t)h * 8 + seg) * NTOK + m] = make_float2(mx, s);
}

__global__ void lse_combine_kernel(const float2* __restrict__ part, float* __restrict__ lse) {
    int m = blockIdx.x * 256 + threadIdx.x;
    int h = blockIdx.y;
    float2 p[8];
    float mx = -3.0e38f;
#pragma unroll
    for (int s = 0; s < 8; s++) {
        p[s] = part[((size_t)h * 8 + s) * NTOK + m];
        mx = fmaxf(mx, p[s].x);
    }
    float sum = 0.f;
#pragma unroll
    for (int s = 0; s < 8; s++) sum += p[s].y * expf(p[s].x - mx);
    lse[h * NTOK + m] = mx + logf(sum);
}

// corr[h][v] = -sum_m lse[h,m] * V[m, h*64+v]
__global__ void corr_kernel(const float* __restrict__ lse, const float* __restrict__ Vb,
                            float* __restrict__ corr) {
    int h = blockIdx.x, t = threadIdx.x;
    int v = t & 63, seg = t >> 6;
    const float* Vp = Vb + h * 64 + v;
    const float* lp = lse + h * NTOK;
    float acc = 0.f;
    for (int m = seg * 512; m < seg * 512 + 512; m++)
        acc = fmaf(lp[m], Vp[(size_t)m * 512], acc);
    __shared__ float red[256];
    red[t] = acc;
    __syncthreads();
    if (t < 64) {
        float tot = red[t] + red[t + 64] + red[t + 128] + red[t + 192];
        corr[h * 64 + t] = -tot;
    }
}

// ---------------- layernorm (ddof=1, no eps, elementwise gain/bias) ----------------
__global__ void layernorm_kernel(const float* __restrict__ in, const float* __restrict__ g,
                                 const float* __restrict__ be, float* __restrict__ out) {
    int n = blockIdx.x, t = threadIdx.x;                   // 128 threads
    size_t base = (size_t)n * 512 + t * 4;
    float4 x = *(const float4*)&in[base];
    float s = x.x + x.y + x.z + x.w;
#pragma unroll
    for (int o = 16; o > 0; o >>= 1) s += __shfl_xor_sync(0xffffffffu, s, o);
    __shared__ float r1[4], r2[4];
    if ((t & 31) == 0) r1[t >> 5] = s;
    __syncthreads();
    float mean = (r1[0] + r1[1] + r1[2] + r1[3]) * (1.0f / 512.0f);
    float d0 = x.x - mean, d1 = x.y - mean, d2 = x.z - mean, d3 = x.w - mean;
    float ss = d0 * d0 + d1 * d1 + d2 * d2 + d3 * d3;
#pragma unroll
    for (int o = 16; o > 0; o >>= 1) ss += __shfl_xor_sync(0xffffffffu, ss, o);
    if ((t & 31) == 0) r2[t >> 5] = ss;
    __syncthreads();
    float var = (r2[0] + r2[1] + r2[2] + r2[3]) * (1.0f / 511.0f);
    float rstd = rsqrtf(var);
    float4 gg = *(const float4*)&g[base];
    float4 bb = *(const float4*)&be[base];
    float4 o4;
    o4.x = fmaf(gg.x * rstd, d0, bb.x);
    o4.y = fmaf(gg.y * rstd, d1, bb.y);
    o4.z = fmaf(gg.z * rstd, d2, bb.z);
    o4.w = fmaf(gg.w * rstd, d3, bb.w);
    *(float4*)&out[base] = o4;
}

// ---------------- orchestration ----------------
extern "C" void kernel_launch(void* const* d_in, const int* in_sizes, int n_in,
                              void* d_out, int out_size) {
    const int* ids = (const int*)d_in[0];
    const float* E = (const float*)d_in[1];
    const float* WQ = (const float*)d_in[2];
    const float* WK = (const float*)d_in[3];
    const float* WV = (const float*)d_in[4];
    const float* WO = (const float*)d_in[5];
    const float* ln1g = (const float*)d_in[6];
    const float* ln1b = (const float*)d_in[7];
    const float* W1 = (const float*)d_in[8];
    const float* b1 = (const float*)d_in[9];
    const float* W2 = (const float*)d_in[10];
    const float* b2 = (const float*)d_in[11];
    const float* ln2g = (const float*)d_in[12];
    const float* ln2b = (const float*)d_in[13];
    float* out = (float*)d_out;
    (void)in_sizes; (void)n_in; (void)out_size;

    float *X, *QKV, *S, *lse, *corr, *Acat, *Z, *F, *P;
    float2* part;
    cudaGetSymbolAddress((void**)&X, g_X);
    cudaGetSymbolAddress((void**)&QKV, g_QKV);
    cudaGetSymbolAddress((void**)&S, g_S);
    cudaGetSymbolAddress((void**)&part, g_part);
    cudaGetSymbolAddress((void**)&lse, g_lse);
    cudaGetSymbolAddress((void**)&corr, g_corr);
    cudaGetSymbolAddress((void**)&Acat, g_A);
    cudaGetSymbolAddress((void**)&Z, g_Z);
    cudaGetSymbolAddress((void**)&F, g_F);
    cudaGetSymbolAddress((void**)&P, g_P);
    float* Q = QKV;
    float* Kb = QKV + NTOK * DMODEL;
    float* Vb = QKV + 2 * NTOK * DMODEL;

    embed_pe<<<NTOK, 128>>>(ids, E, X);

    const long long SNN = (long long)NTOK * NTOK;
    const int redT = 256;

    for (int l = 0; l < NLAYER; l++) {
        const float* WQl = WQ + (size_t)l * NH * DMODEL * DHEAD;
        const float* WKl = WK + (size_t)l * NH * DMODEL * DHEAD;
        const float* WVl = WV + (size_t)l * NH * DMODEL * DHEAD;
        const float* WOl = WO + (size_t)l * DMODEL * DMODEL;
        const float* W1l = W1 + (size_t)l * DMODEL * DFFN;
        const float* b1l = b1 + (size_t)l * DFFN;
        const float* W2l = W2 + (size_t)l * DFFN * DMODEL;
        const float* b2l = b2 + (size_t)l * DMODEL;
        size_t lnOff = (size_t)l * NTOK * DMODEL;

        // ---- fused QKV projections: bz = op*8 + head, 384 blocks ----
        gemm_tc<false, false, true, false><<<dim3(1, 16, 24), 256>>>(
            X, WQl, QKV, DMODEL, DMODEL, DHEAD, DMODEL,
            0LL, (long long)DMODEL * DHEAD, 0LL,
            nullptr, 0, nullptr, 0, 0LL, 1.0f, WKl, WVl, nullptr, 1, 1);

        // ---- S = Q K^T / sqrt(DK) ----
        gemm_tc<true, false, false, false><<<dim3(32, 16, 8), 256>>>(
            Q, Kb, S, DHEAD, DMODEL, DMODEL, NTOK,
            64LL, 64LL, SNN,
            nullptr, 0, nullptr, 0, 0LL, 0.125f, nullptr, nullptr, nullptr, 1, 1);

        // ---- column logsumexp over q, per (h,m) ----
        lse_part_kernel<<<dim3(8, 8, 8), 256>>>(S, part);
        lse_combine_kernel<<<dim3(8, 8), 256>>>(part, lse);
        corr_kernel<<<NH, 256>>>(lse, Vb, corr);

        // ---- attn = S @ V + corr (split-K x4 over K=2048) ----
        gemm_tc<false, false, false, true><<<dim3(1, 16, 32), 256>>>(
            S, Vb, nullptr, NTOK, NTOK, DMODEL, 0,
            SNN, 64LL, 0LL,
            nullptr, 0, nullptr, 0, 0LL, 1.0f, nullptr, nullptr, P, 4, 8);
        reduce_split<<<(NH * NTOK * 64 / 4 + redT - 1) / redT, redT>>>(
            P, Acat, NTOK, 64, DMODEL, 64LL, 4, corr, 64, nullptr, 0, 0LL, 0, NH);

        // ---- Z = Acat @ WO + X (split-K x2) ----
        gemm_tc<false, false, false, true><<<dim3(8, 16, 2), 256>>>(
            Acat, WOl, nullptr, DMODEL, DMODEL, DMODEL, 0,
            0LL, 0LL, 0LL,
            nullptr, 0, nullptr, 0, 0LL, 1.0f, nullptr, nullptr, P, 2, 1);
        reduce_split<<<(NTOK * DMODEL / 4 + redT - 1) / redT, redT>>>(
            P, Z, NTOK, DMODEL, DMODEL, 0LL, 2, nullptr, 0, X, DMODEL, 0LL, 0, 1);
        layernorm_kernel<<<NTOK, 128>>>(Z, ln1g + lnOff, ln1b + lnOff, Z);

        // ---- F = relu(Z @ W1 + b1) ----
        gemm_tc<false, true, false, false><<<dim3(32, 16, 1), 256>>>(
            Z, W1l, F, DMODEL, DMODEL, DFFN, DFFN,
            0LL, 0LL, 0LL,
            b1l, 0, nullptr, 0, 0LL, 1.0f, nullptr, nullptr, nullptr, 1, 1);

        // ---- X = F @ W2 + b2 + Z (split-K x4) ----
        gemm_tc<false, false, false, true><<<dim3(8, 16, 4), 256>>>(
            F, W2l, nullptr, DFFN, DFFN, DMODEL, 0,
            0LL, 0LL, 0LL,
            nullptr, 0, nullptr, 0, 0LL, 1.0f, nullptr, nullptr, P, 4, 1);
        reduce_split<<<(NTOK * DMODEL / 4 + redT - 1) / redT, redT>>>(
            P, X, NTOK, DMODEL, DMODEL, 0LL, 4, b2l, 0, Z, DMODEL, 0LL, 0, 1);
        layernorm_kernel<<<NTOK, 128>>>(X, ln2g + lnOff, ln2b + lnOff,
                                        (l == NLAYER - 1) ? out : X);
    }
}

// round 7
// speedup vs baseline: 2.8650x; 1.2950x over previous
#include <cuda_runtime.h>
#include <cstdint>

#define NTOK   2048
#define DMODEL 512
#define DFFN   2048
#define NH     8
#define DHEAD  64
#define NLAYER 6

// ---------------- device scratch (static, no allocation) ----------------
__device__ float g_X[NTOK * DMODEL];
__device__ float g_QKV[3 * NTOK * DMODEL];               // Q | K | V planes
__device__ float2 g_part[NH * 16 * NTOK];                // lse partials (2 MB)
__device__ float g_lse[NH * NTOK];
__device__ float g_corr[NH * DHEAD];
__device__ float g_KVp[NH * 16 * DHEAD * DHEAD];         // K^T V partials (2 MB)
__device__ float g_G[NH * DHEAD * DHEAD];                // K^T V / 8 per head
__device__ float g_A[NTOK * DMODEL];
__device__ float g_Z[NTOK * DMODEL];
__device__ float g_F[NTOK * DFFN];
__device__ float g_P[4 * NTOK * DMODEL];                 // split-K partials (16 MB)

// ---------------- fast exp (FMA-only, no MUFU) ----------------
__device__ __forceinline__ float fexp(float x) {
    x = fmaxf(x, -87.0f);
    float t = x * 1.4426950408889634f;
    const float big = 12582912.0f;
    float r = __fadd_rn(t, big) - big;
    float f = t - r;
    float p = 1.5403530e-4f;
    p = fmaf(p, f, 1.33335581e-3f);
    p = fmaf(p, f, 9.61812911e-3f);
    p = fmaf(p, f, 5.55041087e-2f);
    p = fmaf(p, f, 2.40226507e-1f);
    p = fmaf(p, f, 6.93147181e-1f);
    p = fmaf(p, f, 1.0f);
    int e = (int)r;
    return p * __int_as_float((e + 127) << 23);
}

// ---------------- bf16 / mma helpers ----------------
__device__ __forceinline__ uint32_t packbf(float e0, float e1) {  // e0 -> bits[15:0]
    uint32_t r;
    asm("cvt.rn.bf16x2.f32 %0, %1, %2;" : "=r"(r) : "f"(e1), "f"(e0));
    return r;
}
__device__ __forceinline__ float lo_f(uint32_t p) { return __uint_as_float(p << 16); }
__device__ __forceinline__ float hi_f(uint32_t p) { return __uint_as_float(p & 0xffff0000u); }

__device__ __forceinline__ void cvt_store4(char* hiP, char* loP, float4 v) {
    uint32_t h01 = packbf(v.x, v.y), h23 = packbf(v.z, v.w);
    uint32_t l01 = packbf(v.x - lo_f(h01), v.y - hi_f(h01));
    uint32_t l23 = packbf(v.z - lo_f(h23), v.w - hi_f(h23));
    *(uint2*)hiP = make_uint2(h01, h23);
    *(uint2*)loP = make_uint2(l01, l23);
}

__device__ __forceinline__ void ldsm4(uint32_t r[4], uint32_t addr) {
    asm volatile("ldmatrix.sync.aligned.m8n8.x4.shared.b16 {%0,%1,%2,%3}, [%4];"
                 : "=r"(r[0]), "=r"(r[1]), "=r"(r[2]), "=r"(r[3]) : "r"(addr));
}
__device__ __forceinline__ void ldsm4t(uint32_t r[4], uint32_t addr) {
    asm volatile("ldmatrix.sync.aligned.m8n8.x4.trans.shared.b16 {%0,%1,%2,%3}, [%4];"
                 : "=r"(r[0]), "=r"(r[1]), "=r"(r[2]), "=r"(r[3]) : "r"(addr));
}
__device__ __forceinline__ void mma_bf16(float d[4], const uint32_t a[4],
                                         uint32_t b0, uint32_t b1) {
    asm volatile(
        "mma.sync.aligned.m16n8k16.row.col.f32.bf16.bf16.f32 "
        "{%0,%1,%2,%3}, {%4,%5,%6,%7}, {%8,%9}, {%0,%1,%2,%3};"
        : "+f"(d[0]), "+f"(d[1]), "+f"(d[2]), "+f"(d[3])
        : "r"(a[0]), "r"(a[1]), "r"(a[2]), "r"(a[3]), "r"(b0), "r"(b1));
}

// ---------------- embedding + positional encoding ----------------
__global__ void embed_pe(const int* __restrict__ ids, const float* __restrict__ E,
                         float* __restrict__ X) {
    int n = blockIdx.x, t = threadIdx.x;                  // 128 threads
    int id = ids[n];
    float4 e = *(const float4*)&E[(size_t)id * DMODEL + t * 4];
    float ev[4] = {e.x, e.y, e.z, e.w};
    float pos = (float)(n + 1);
    float ov[4];
#pragma unroll
    for (int i = 0; i < 4; i++) {
        int d = t * 4 + i;
        int de = d & ~1;
        float f = expf((float)de * (-9.210340371976184f / 512.0f));
        float arg = pos * f;
        float pe = (d & 1) ? cosf(arg) : sinf(arg);
        ov[i] = ev[i] + pe;
    }
    *(float4*)&X[(size_t)n * DMODEL + t * 4] = *(float4*)ov;
}

// ---------------- bf16x3 tensor-core GEMM (fp32-grade accuracy) ----------------
// NN only. C = alpha*A*B + bias + res, optional relu; or raw partials (split-K).
template <bool RELU, bool QKV, bool SPLITK>
__global__ void __launch_bounds__(256, 2)
gemm_tc(const float* __restrict__ Ag, const float* __restrict__ Bg,
        float* __restrict__ Cg, int K, int lda, int ldb, int ldc,
        long long sA, long long sB, long long sC,
        const float* __restrict__ biasg, int sBias,
        const float* __restrict__ resg, int ldr, long long sR,
        float alpha,
        const float* __restrict__ Bg1, const float* __restrict__ Bg2,
        float* __restrict__ Pbuf, int nsplit, int zInner) {
    __shared__ __align__(16) char sm[20480 + 8192];       // A hi/lo 2x10240, B hi/lo 2x4096
    char* Ahi = sm;
    char* Alo = sm + 10240;
    char* Bhi = sm + 20480;
    char* Blo = sm + 20480 + 4096;

    const int tid = threadIdx.x;
    const int bz = blockIdx.z;
    int bzIn = bz, split = 0;
    if (SPLITK) { bzIn = bz % zInner; split = bz / zInner; }
    const int kLen = SPLITK ? K / nsplit : K;
    const int kStart = SPLITK ? split * kLen : 0;

    const float* A = Ag + (size_t)bzIn * sA + (size_t)blockIdx.y * 128 * lda + kStart;
    const float* B;
    if (QKV) {
        int op = bz >> 3;
        const float* Bsel = (op == 0) ? Bg : (op == 1 ? Bg1 : Bg2);
        B = Bsel + (size_t)(bz & 7) * sB;
    } else {
        B = Bg + (size_t)bzIn * sB + (size_t)kStart * ldb + (size_t)blockIdx.x * 64;
    }

    const int ar = tid >> 3, ac = tid & 7;                // A loader coords
    const int kk_ld = tid >> 4, nb4 = (tid & 15) * 4;     // B loader coords

    float4 aR[4], bR[2];

    auto ldgA = [&](int k0) {
#pragma unroll
        for (int i = 0; i < 4; i++)
            aR[i] = *(const float4*)&A[(size_t)(ar + i * 32) * lda + k0 + ac * 4];
    };
    auto ldgB = [&](int k0) {
#pragma unroll
        for (int i = 0; i < 2; i++)
            bR[i] = *(const float4*)&B[(size_t)(k0 + kk_ld + i * 16) * ldb + nb4];
    };
    auto stsA = [&]() {
#pragma unroll
        for (int i = 0; i < 4; i++) {
            int off = (ar + i * 32) * 80 + ac * 8;        // 80B-pitch rows
            cvt_store4(Ahi + off, Alo + off, aR[i]);
        }
    };
    auto stsB = [&]() {
#pragma unroll
        for (int i = 0; i < 2; i++) {
            int k = kk_ld + i * 16;                       // [k][n] 128B rows, swizzled
            int off = k * 128 + (((nb4 >> 3) ^ (k & 7)) << 4) + ((nb4 & 4) << 1);
            cvt_store4(Bhi + off, Blo + off, bR[i]);
        }
    };

    const int lane = tid & 31, warp = tid >> 5;
    const int wm = (warp & 3) << 5, wn = (warp >> 2) << 5;
    uint32_t sm_u = (uint32_t)__cvta_generic_to_shared(sm);
    const uint32_t aBase = sm_u + (uint32_t)((wm + (lane & 15)) * 80 + (lane >> 4) * 16);
    const int krowL = (lane & 7) + ((lane >> 4) << 3);
    const int chnkL = (wn >> 3) + ((lane >> 3) & 1);

    float d[2][4][4];
#pragma unroll
    for (int i = 0; i < 2; i++)
#pragma unroll
        for (int j = 0; j < 4; j++)
#pragma unroll
            for (int q = 0; q < 4; q++) d[i][j][q] = 0.f;

    ldgA(0); ldgB(0);
    stsA(); stsB();
    __syncthreads();

    const int nkt = kLen >> 5;
    for (int kt = 0; kt < nkt; kt++) {
        if (kt + 1 < nkt) { ldgA((kt + 1) << 5); ldgB((kt + 1) << 5); }
#pragma unroll
        for (int ks = 0; ks < 2; ks++) {
            uint32_t ah[2][4], al[2][4], bh[2][4], bl[2][4];
#pragma unroll
            for (int mb = 0; mb < 2; mb++) {
                uint32_t a = aBase + (uint32_t)(mb * 16 * 80 + ks * 32);
                ldsm4(ah[mb], a);
                ldsm4(al[mb], a + 10240u);
            }
#pragma unroll
            for (int g = 0; g < 2; g++) {
                int k = ks * 16 + krowL;
                uint32_t b = sm_u + 20480u +
                             (uint32_t)(k * 128 + (((chnkL + g * 2) ^ (k & 7)) << 4));
                ldsm4t(bh[g], b);
                ldsm4t(bl[g], b + 4096u);
            }
#pragma unroll
            for (int mb = 0; mb < 2; mb++)
#pragma unroll
                for (int nb = 0; nb < 4; nb++) {
                    int g = nb >> 1, j = nb & 1;
                    uint32_t B0 = bh[g][j], B1 = bh[g][j + 2];
                    mma_bf16(d[mb][nb], ah[mb], B0, B1);
                    mma_bf16(d[mb][nb], ah[mb], bl[g][j], bl[g][j + 2]);
                    mma_bf16(d[mb][nb], al[mb], B0, B1);
                }
        }
        __syncthreads();
        if (kt + 1 < nkt) { stsA(); stsB(); __syncthreads(); }
    }

    const int gr = lane >> 2, gc = (lane & 3) * 2;
    const int mBase = blockIdx.y * 128 + wm;
    const int nBase = blockIdx.x * 64 + wn;
    if (SPLITK) {
        const int Mfull = gridDim.y * 128, Nfull = gridDim.x * 64;
        float* P = Pbuf + (size_t)(split * zInner + bzIn) * Mfull * Nfull;
#pragma unroll
        for (int mb = 0; mb < 2; mb++)
#pragma unroll
            for (int nb = 0; nb < 4; nb++)
#pragma unroll
                for (int h2 = 0; h2 < 2; h2++) {
                    int m = mBase + mb * 16 + gr + h2 * 8;
                    int n = nBase + nb * 8 + gc;
                    *(float2*)&P[(size_t)m * Nfull + n] =
                        make_float2(d[mb][nb][h2 * 2] * alpha, d[mb][nb][h2 * 2 + 1] * alpha);
                }
        return;
    }
    float* C;
    if (QKV) {
        C = Cg + (size_t)(bz >> 3) * (NTOK * DMODEL) + (size_t)(bz & 7) * 64;
    } else {
        C = Cg + (size_t)bzIn * sC;
    }
    const float* bi = biasg ? biasg + (size_t)bzIn * sBias : nullptr;
    const float* Rg = resg ? resg + (size_t)bzIn * sR : nullptr;
#pragma unroll
    for (int mb = 0; mb < 2; mb++)
#pragma unroll
        for (int nb = 0; nb < 4; nb++)
#pragma unroll
            for (int h2 = 0; h2 < 2; h2++) {
                int m = mBase + mb * 16 + gr + h2 * 8;
                int n = nBase + nb * 8 + gc;
                float v0 = d[mb][nb][h2 * 2] * alpha;
                float v1 = d[mb][nb][h2 * 2 + 1] * alpha;
                if (bi) {
                    float2 bb = *(const float2*)&bi[n];
                    v0 += bb.x; v1 += bb.y;
                }
                if (Rg) {
                    float2 rr = *(const float2*)&Rg[(size_t)m * ldr + n];
                    v0 += rr.x; v1 += rr.y;
                }
                if (RELU) { v0 = fmaxf(v0, 0.f); v1 = fmaxf(v1, 0.f); }
                *(float2*)&C[(size_t)m * ldc + n] = make_float2(v0, v1);
            }
}

// ---------------- fused QK^T tile + column (max, sumexp) partials ----------------
// Grid: (mtile=32, qtile=16, head=8). Computes S-tile = Q K^T / 8 on tensor cores,
// reduces over the 128 q-rows per column, writes one float2 per column.
__global__ void __launch_bounds__(256, 2)
qk_lse(const float* __restrict__ Qg, const float* __restrict__ Kg,
       float2* __restrict__ part) {
    __shared__ __align__(16) char sm[20480 + 10240];      // A 2x10240, B 2x5120
    char* Ahi = sm;
    char* Alo = sm + 10240;
    char* Bhi = sm + 20480;
    char* Blo = sm + 20480 + 5120;

    const int tid = threadIdx.x;
    const int h = blockIdx.z;
    const float* A = Qg + h * 64 + (size_t)blockIdx.y * 128 * DMODEL;
    const float* B = Kg + h * 64 + (size_t)blockIdx.x * 64 * DMODEL;

    const int ar = tid >> 3, ac = tid & 7;

    float4 aR[4], bR[2];
#pragma unroll
    for (int i = 0; i < 4; i++)
        aR[i] = *(const float4*)&A[(size_t)(ar + i * 32) * DMODEL + ac * 4];
#pragma unroll
    for (int i = 0; i < 2; i++)
        bR[i] = *(const float4*)&B[(size_t)(ar + i * 32) * DMODEL + ac * 4];

    const int lane = tid & 31, warp = tid >> 5;
    const int wm = (warp & 3) << 5, wn = (warp >> 2) << 5;
    uint32_t sm_u = (uint32_t)__cvta_generic_to_shared(sm);
    const uint32_t aBase = sm_u + (uint32_t)((wm + (lane & 15)) * 80 + (lane >> 4) * 16);
    const uint32_t bBase = sm_u + 20480u + (uint32_t)((wn + (lane & 15)) * 80 + (lane >> 4) * 16);

    float d[2][4][4];
#pragma unroll
    for (int i = 0; i < 2; i++)
#pragma unroll
        for (int j = 0; j < 4; j++)
#pragma unroll
            for (int q = 0; q < 4; q++) d[i][j][q] = 0.f;

#pragma unroll
    for (int kt = 0; kt < 2; kt++) {
        {
#pragma unroll
            for (int i = 0; i < 4; i++) {
                int off = (ar + i * 32) * 80 + ac * 8;
                cvt_store4(Ahi + off, Alo + off, aR[i]);
            }
#pragma unroll
            for (int i = 0; i < 2; i++) {
                int off = (ar + i * 32) * 80 + ac * 8;
                cvt_store4(Bhi + off, Blo + off, bR[i]);
            }
        }
        __syncthreads();
        if (kt == 0) {
#pragma unroll
            for (int i = 0; i < 4; i++)
                aR[i] = *(const float4*)&A[(size_t)(ar + i * 32) * DMODEL + 32 + ac * 4];
#pragma unroll
            for (int i = 0; i < 2; i++)
                bR[i] = *(const float4*)&B[(size_t)(ar + i * 32) * DMODEL + 32 + ac * 4];
        }
#pragma unroll
        for (int ks = 0; ks < 2; ks++) {
            uint32_t ah[2][4], al[2][4], bh[2][4], bl[2][4];
#pragma unroll
            for (int mb = 0; mb < 2; mb++) {
                uint32_t a = aBase + (uint32_t)(mb * 16 * 80 + ks * 32);
                ldsm4(ah[mb], a);
                ldsm4(al[mb], a + 10240u);
            }
#pragma unroll
            for (int g = 0; g < 2; g++) {
                uint32_t b = bBase + (uint32_t)(g * 16 * 80 + ks * 32);
                ldsm4(bh[g], b);
                ldsm4(bl[g], b + 5120u);
            }
#pragma unroll
            for (int mb = 0; mb < 2; mb++)
#pragma unroll
                for (int nb = 0; nb < 4; nb++) {
                    int g = nb >> 1, j = nb & 1;
                    uint32_t B0 = bh[g][j], B1 = bh[g][j + 2];
                    mma_bf16(d[mb][nb], ah[mb], B0, B1);
                    mma_bf16(d[mb][nb], ah[mb], bl[g][j], bl[g][j + 2]);
                    mma_bf16(d[mb][nb], al[mb], B0, B1);
                }
        }
        __syncthreads();
    }

    // ---- per-column (max, sumexp) over this block's 128 q-rows ----
    const int gc0 = (lane & 3) * 2;
    float cm[8], cs[8];
#pragma unroll
    for (int idx = 0; idx < 8; idx++) {
        int nb = idx >> 1, j = idx & 1;
        float v0 = d[0][nb][j] * 0.125f;
        float v1 = d[0][nb][2 + j] * 0.125f;
        float v2 = d[1][nb][j] * 0.125f;
        float v3 = d[1][nb][2 + j] * 0.125f;
        float m = fmaxf(fmaxf(v0, v1), fmaxf(v2, v3));
        cm[idx] = m;
        cs[idx] = fexp(v0 - m) + fexp(v1 - m) + fexp(v2 - m) + fexp(v3 - m);
    }
#pragma unroll
    for (int off = 4; off <= 16; off <<= 1) {
#pragma unroll
        for (int idx = 0; idx < 8; idx++) {
            float om = __shfl_xor_sync(0xffffffffu, cm[idx], off);
            float os = __shfl_xor_sync(0xffffffffu, cs[idx], off);
            float nm = fmaxf(cm[idx], om);
            cs[idx] = cs[idx] * fexp(cm[idx] - nm) + os * fexp(om - nm);
            cm[idx] = nm;
        }
    }
    float2* psm = (float2*)sm;                            // [4][64], aliases mainloop smem
    if (lane < 4) {
#pragma unroll
        for (int idx = 0; idx < 8; idx++) {
            int nb = idx >> 1, j = idx & 1;
            int col = wn + gc0 + j + nb * 8;
            psm[(warp & 3) * 64 + col] = make_float2(cm[idx], cs[idx]);
        }
    }
    __syncthreads();
    if (tid < 64) {
        float2 a = psm[tid];
        float m = a.x, s = a.y;
#pragma unroll
        for (int w = 1; w < 4; w++) {
            float2 b = psm[w * 64 + tid];
            float nm = fmaxf(m, b.x);
            s = s * fexp(m - nm) + b.y * fexp(b.x - nm);
            m = nm;
        }
        part[((size_t)h * 16 + blockIdx.y) * NTOK + blockIdx.x * 64 + tid] =
            make_float2(m, s);
    }
}

__global__ void lse_combine_kernel(const float2* __restrict__ part, float* __restrict__ lse) {
    int m = blockIdx.x * 256 + threadIdx.x;
    int h = blockIdx.y;
    float mx = -3.0e38f;
    float2 p[16];
#pragma unroll
    for (int s = 0; s < 16; s++) {
        p[s] = part[((size_t)h * 16 + s) * NTOK + m];
        mx = fmaxf(mx, p[s].x);
    }
    float sum = 0.f;
#pragma unroll
    for (int s = 0; s < 16; s++) sum += p[s].y * expf(p[s].x - mx);
    lse[h * NTOK + m] = mx + logf(sum);
}

// corr[h][v] = -sum_m lse[h,m] * V[m, h*64+v]
__global__ void corr_kernel(const float* __restrict__ lse, const float* __restrict__ Vb,
                            float* __restrict__ corr) {
    int h = blockIdx.x, t = threadIdx.x;
    int v = t & 63, seg = t >> 6;
    const float* Vp = Vb + h * 64 + v;
    const float* lp = lse + h * NTOK;
    float acc = 0.f;
    for (int m = seg * 512; m < seg * 512 + 512; m++)
        acc = fmaf(lp[m], Vp[(size_t)m * 512], acc);
    __shared__ float red[256];
    red[t] = acc;
    __syncthreads();
    if (t < 64) {
        float tot = red[t] + red[t + 64] + red[t + 128] + red[t + 192];
        corr[h * 64 + t] = -tot;
    }
}

// ---------------- K^T V rank-update partials: per (head, m-chunk of 128) ----------------
__global__ void __launch_bounds__(256)
ktv_kernel(const float* __restrict__ Kg, const float* __restrict__ Vg,
           float* __restrict__ Pk) {
    const int chunk = blockIdx.x, h = blockIdx.y;
    const int tid = threadIdx.x;
    const int td = tid & 15, tv = tid >> 4;               // 16x16 thread grid, 4x4 tiles
    __shared__ float sk[8][64], sv[8][64];
    const float* Kp = Kg + h * 64;
    const float* Vp = Vg + h * 64;
    const int m0 = chunk * 128;

    float acc[4][4];
#pragma unroll
    for (int i = 0; i < 4; i++)
#pragma unroll
        for (int j = 0; j < 4; j++) acc[i][j] = 0.f;

    for (int mb = 0; mb < 128; mb += 8) {
        __syncthreads();
#pragma unroll
        for (int r = 0; r < 2; r++) {
            int i = tid + r * 256;
            int mi = i >> 6, c = i & 63;
            sk[mi][c] = Kp[(size_t)(m0 + mb + mi) * DMODEL + c];
            sv[mi][c] = Vp[(size_t)(m0 + mb + mi) * DMODEL + c];
        }
        __syncthreads();
#pragma unroll
        for (int mi = 0; mi < 8; mi++) {
            float4 kk = *(const float4*)&sk[mi][td * 4];
            float4 vv = *(const float4*)&sv[mi][tv * 4];
            float ka[4] = {kk.x, kk.y, kk.z, kk.w};
            float va[4] = {vv.x, vv.y, vv.z, vv.w};
#pragma unroll
            for (int i = 0; i < 4; i++)
#pragma unroll
                for (int j = 0; j < 4; j++)
                    acc[i][j] = fmaf(ka[i], va[j], acc[i][j]);
        }
    }
    float* P = Pk + ((size_t)h * 16 + chunk) * (DHEAD * DHEAD);
#pragma unroll
    for (int i = 0; i < 4; i++)
        *(float4*)&P[(td * 4 + i) * 64 + tv * 4] = *(float4*)acc[i];
}

// G[h] = 0.125 * sum over 16 chunks
__global__ void ktv_reduce(const float* __restrict__ Pk, float* __restrict__ G) {
    int idx = blockIdx.x * 256 + threadIdx.x;             // 8192 float4's
    int h = idx >> 10, e = (idx & 1023) * 4;
    const float* P = Pk + (size_t)h * 16 * (DHEAD * DHEAD) + e;
    float4 v = *(const float4*)P;
#pragma unroll
    for (int c = 1; c < 16; c++) {
        float4 p = *(const float4*)&P[c * DHEAD * DHEAD];
        v.x += p.x; v.y += p.y; v.z += p.z; v.w += p.w;
    }
    v.x *= 0.125f; v.y *= 0.125f; v.z *= 0.125f; v.w *= 0.125f;
    *(float4*)&G[(size_t)h * DHEAD * DHEAD + e] = v;
}

// ---------------- split-K reduction + epilogue (deterministic order) ----------------
__global__ void reduce_split(const float* __restrict__ P, float* __restrict__ C,
                             int M, int Nn, int ldc, long long sC, int nsplit,
                             const float* __restrict__ bias, int sBias,
                             const float* __restrict__ res, int ldr, long long sR,
                             int relu, int batch) {
    size_t perBatch = (size_t)M * Nn;
    size_t total4 = (size_t)batch * perBatch / 4;
    size_t idx = (size_t)blockIdx.x * blockDim.x + threadIdx.x;
    if (idx >= total4) return;
    size_t e4 = idx * 4;
    int b = (int)(e4 / perBatch);
    size_t r = e4 % perBatch;
    int m = (int)(r / Nn);
    int n = (int)(r % Nn);
    size_t splitStride = (size_t)batch * perBatch;
    float4 v = *(const float4*)&P[e4];
    for (int s = 1; s < nsplit; s++) {
        float4 p = *(const float4*)&P[(size_t)s * splitStride + e4];
        v.x += p.x; v.y += p.y; v.z += p.z; v.w += p.w;
    }
    if (bias) {
        const float* bi = bias + (size_t)b * sBias;
        v.x += bi[n]; v.y += bi[n + 1]; v.z += bi[n + 2]; v.w += bi[n + 3];
    }
    if (res) {
        float4 r4 = *(const float4*)&res[(size_t)b * sR + (size_t)m * ldr + n];
        v.x += r4.x; v.y += r4.y; v.z += r4.z; v.w += r4.w;
    }
    if (relu) {
        v.x = fmaxf(v.x, 0.f); v.y = fmaxf(v.y, 0.f);
        v.z = fmaxf(v.z, 0.f); v.w = fmaxf(v.w, 0.f);
    }
    *(float4*)&C[(size_t)b * sC + (size_t)m * ldc + n] = v;
}

// ---------------- layernorm (ddof=1, no eps, elementwise gain/bias) ----------------
__global__ void layernorm_kernel(const float* __restrict__ in, const float* __restrict__ g,
                                 const float* __restrict__ be, float* __restrict__ out) {
    int n = blockIdx.x, t = threadIdx.x;                   // 128 threads
    size_t base = (size_t)n * 512 + t * 4;
    float4 x = *(const float4*)&in[base];
    float s = x.x + x.y + x.z + x.w;
#pragma unroll
    for (int o = 16; o > 0; o >>= 1) s += __shfl_xor_sync(0xffffffffu, s, o);
    __shared__ float r1[4], r2[4];
    if ((t & 31) == 0) r1[t >> 5] = s;
    __syncthreads();
    float mean = (r1[0] + r1[1] + r1[2] + r1[3]) * (1.0f / 512.0f);
    float d0 = x.x - mean, d1 = x.y - mean, d2 = x.z - mean, d3 = x.w - mean;
    float ss = d0 * d0 + d1 * d1 + d2 * d2 + d3 * d3;
#pragma unroll
    for (int o = 16; o > 0; o >>= 1) ss += __shfl_xor_sync(0xffffffffu, ss, o);
    if ((t & 31) == 0) r2[t >> 5] = ss;
    __syncthreads();
    float var = (r2[0] + r2[1] + r2[2] + r2[3]) * (1.0f / 511.0f);
    float rstd = rsqrtf(var);
    float4 gg = *(const float4*)&g[base];
    float4 bb = *(const float4*)&be[base];
    float4 o4;
    o4.x = fmaf(gg.x * rstd, d0, bb.x);
    o4.y = fmaf(gg.y * rstd, d1, bb.y);
    o4.z = fmaf(gg.z * rstd, d2, bb.z);
    o4.w = fmaf(gg.w * rstd, d3, bb.w);
    *(float4*)&out[base] = o4;
}

// ---------------- orchestration ----------------
extern "C" void kernel_launch(void* const* d_in, const int* in_sizes, int n_in,
                              void* d_out, int out_size) {
    const int* ids = (const int*)d_in[0];
    const float* E = (const float*)d_in[1];
    const float* WQ = (const float*)d_in[2];
    const float* WK = (const float*)d_in[3];
    const float* WV = (const float*)d_in[4];
    const float* WO = (const float*)d_in[5];
    const float* ln1g = (const float*)d_in[6];
    const float* ln1b = (const float*)d_in[7];
    const float* W1 = (const float*)d_in[8];
    const float* b1 = (const float*)d_in[9];
    const float* W2 = (const float*)d_in[10];
    const float* b2 = (const float*)d_in[11];
    const float* ln2g = (const float*)d_in[12];
    const float* ln2b = (const float*)d_in[13];
    float* out = (float*)d_out;
    (void)in_sizes; (void)n_in; (void)out_size;

    float *X, *QKV, *lse, *corr, *KVp, *G, *Acat, *Z, *F, *P;
    float2* part;
    cudaGetSymbolAddress((void**)&X, g_X);
    cudaGetSymbolAddress((void**)&QKV, g_QKV);
    cudaGetSymbolAddress((void**)&part, g_part);
    cudaGetSymbolAddress((void**)&lse, g_lse);
    cudaGetSymbolAddress((void**)&corr, g_corr);
    cudaGetSymbolAddress((void**)&KVp, g_KVp);
    cudaGetSymbolAddress((void**)&G, g_G);
    cudaGetSymbolAddress((void**)&Acat, g_A);
    cudaGetSymbolAddress((void**)&Z, g_Z);
    cudaGetSymbolAddress((void**)&F, g_F);
    cudaGetSymbolAddress((void**)&P, g_P);
    float* Q = QKV;
    float* Kb = QKV + NTOK * DMODEL;
    float* Vb = QKV + 2 * NTOK * DMODEL;

    embed_pe<<<NTOK, 128>>>(ids, E, X);

    const int redT = 256;

    for (int l = 0; l < NLAYER; l++) {
        const float* WQl = WQ + (size_t)l * NH * DMODEL * DHEAD;
        const float* WKl = WK + (size_t)l * NH * DMODEL * DHEAD;
        const float* WVl = WV + (size_t)l * NH * DMODEL * DHEAD;
        const float* WOl = WO + (size_t)l * DMODEL * DMODEL;
        const float* W1l = W1 + (size_t)l * DMODEL * DFFN;
        const float* b1l = b1 + (size_t)l * DFFN;
        const float* W2l = W2 + (size_t)l * DFFN * DMODEL;
        const float* b2l = b2 + (size_t)l * DMODEL;
        size_t lnOff = (size_t)l * NTOK * DMODEL;

        // ---- fused QKV projections: bz = op*8 + head ----
        gemm_tc<false, true, false><<<dim3(1, 16, 24), 256>>>(
            X, WQl, QKV, DMODEL, DMODEL, DHEAD, DMODEL,
            0LL, (long long)DMODEL * DHEAD, 0LL,
            nullptr, 0, nullptr, 0, 0LL, 1.0f, WKl, WVl, nullptr, 1, 1);

        // ---- fused QK^T/8 + column-lse partials (no S materialization) ----
        qk_lse<<<dim3(32, 16, 8), 256>>>(Q, Kb, part);
        lse_combine_kernel<<<dim3(8, 8), 256>>>(part, lse);
        corr_kernel<<<NH, 256>>>(lse, Vb, corr);

        // ---- G_h = K_h^T V_h / 8 (rank-2048 update, FMA) ----
        ktv_kernel<<<dim3(16, 8), 256>>>(Kb, Vb, KVp);
        ktv_reduce<<<32, 256>>>(KVp, G);

        // ---- attn = Q @ G + corr ----
        gemm_tc<false, false, false><<<dim3(1, 16, 8), 256>>>(
            Q, G, Acat, DHEAD, DMODEL, DHEAD, DMODEL,
            64LL, (long long)DHEAD * DHEAD, 64LL,
            corr, 64, nullptr, 0, 0LL, 1.0f, nullptr, nullptr, nullptr, 1, 1);

        // ---- Z = Acat @ WO + X (split-K x2) ----
        gemm_tc<false, false, true><<<dim3(8, 16, 2), 256>>>(
            Acat, WOl, nullptr, DMODEL, DMODEL, DMODEL, 0,
            0LL, 0LL, 0LL,
            nullptr, 0, nullptr, 0, 0LL, 1.0f, nullptr, nullptr, P, 2, 1);
        reduce_split<<<(NTOK * DMODEL / 4 + redT - 1) / redT, redT>>>(
            P, Z, NTOK, DMODEL, DMODEL, 0LL, 2, nullptr, 0, X, DMODEL, 0LL, 0, 1);
        layernorm_kernel<<<NTOK, 128>>>(Z, ln1g + lnOff, ln1b + lnOff, Z);

        // ---- F = relu(Z @ W1 + b1) ----
        gemm_tc<true, false, false><<<dim3(32, 16, 1), 256>>>(
            Z, W1l, F, DMODEL, DMODEL, DFFN, DFFN,
            0LL, 0LL, 0LL,
            b1l, 0, nullptr, 0, 0LL, 1.0f, nullptr, nullptr, nullptr, 1, 1);

        // ---- X = F @ W2 + b2 + Z (split-K x4) ----
        gemm_tc<false, false, true><<<dim3(8, 16, 4), 256>>>(
            F, W2l, nullptr, DFFN, DFFN, DMODEL, 0,
            0LL, 0LL, 0LL,
            nullptr, 0, nullptr, 0, 0LL, 1.0f, nullptr, nullptr, P, 4, 1);
        reduce_split<<<(NTOK * DMODEL / 4 + redT - 1) / redT, redT>>>(
            P, X, NTOK, DMODEL, DMODEL, 0LL, 4, b2l, 0, Z, DMODEL, 0LL, 0, 1);
        layernorm_kernel<<<NTOK, 128>>>(X, ln2g + lnOff, ln2b + lnOff,
                                        (l == NLAYER - 1) ? out : X);
    }
}